// round 3
// baseline (speedup 1.0000x reference)
#include <cuda_runtime.h>
#include <math.h>

// ---------------------------------------------------------------------------
// Problem constants
// ---------------------------------------------------------------------------
#define NMAX   50000
#define EMAX   800000
#define GMAX   1024
#define HIDC   128
#define H3C    384
#define NEGS   0.01f

// ---------------------------------------------------------------------------
// Scratch (device globals; no allocation allowed)
// ---------------------------------------------------------------------------
__device__ float g_X  [(size_t)NMAX * HIDC];   // node features
__device__ float g_Z  [(size_t)NMAX * HIDC];   // transformed features (messages)
__device__ float g_H  [(size_t)NMAX * HIDC];   // temp / aggregation buffer
__device__ float g_GI [(size_t)NMAX * H3C];    // GRU input gates
__device__ float g_GH [(size_t)NMAX * H3C];    // GRU hidden gates
__device__ float g_al [NMAX];                  // per-node scalar (src attn)
__device__ float g_ar [NMAX];                  // per-node scalar (dst attn)
__device__ float g_m  [NMAX];                  // segment max
__device__ float g_sum[NMAX];                  // segment sum
__device__ float g_cE [HIDC];                  // GATE edge-constant bias
__device__ float g_OUT [GMAX * HIDC];
__device__ float g_OT  [GMAX * HIDC];
__device__ float g_H2  [GMAX * HIDC];
__device__ float g_GI2 [GMAX * H3C];
__device__ float g_GH2 [GMAX * H3C];
__device__ float g_ad  [GMAX];

// ---------------------------------------------------------------------------
// Helpers
// ---------------------------------------------------------------------------
__device__ __forceinline__ float leaky_f(float v) { return v >= 0.f ? v : NEGS * v; }

__device__ __forceinline__ void atomicMaxFloat(float* addr, float val) {
    if (val >= 0.f) atomicMax((int*)addr, __float_as_int(val));
    else            atomicMin((unsigned int*)addr, __float_as_uint(val));
}

// ---------------------------------------------------------------------------
// Generic NT GEMM: C[N,M] = act(A[N,K(lda)] * W[M,K(ldw)]^T + bias)
// act: 0 = none, 1 = leaky_relu(0.01)
// ---------------------------------------------------------------------------
template<int BM, int BN, int BK, int TM, int TN>
__global__ __launch_bounds__((BM/TM)*(BN/TN))
void gemm_nt(const float* __restrict__ A, int lda,
             const float* __restrict__ W, int ldw,
             const float* __restrict__ bias,
             float* __restrict__ C, int ldc,
             int N, int M, int K, int act)
{
    constexpr int NTH = (BM/TM) * (BN/TN);
    __shared__ __align__(16) float As[BK][BM];
    __shared__ __align__(16) float Ws[BK][BN];

    const int tid  = threadIdx.x;
    const int row0 = blockIdx.y * BM;
    const int col0 = blockIdx.x * BN;
    const int trow = (tid / (BN/TN)) * TM;
    const int tcol = (tid % (BN/TN)) * TN;

    float acc[TM][TN];
    #pragma unroll
    for (int i = 0; i < TM; i++)
        #pragma unroll
        for (int j = 0; j < TN; j++) acc[i][j] = 0.f;

    for (int k0 = 0; k0 < K; k0 += BK) {
        #pragma unroll
        for (int i = tid; i < BM * BK; i += NTH) {
            int mm = i / BK, kk = i % BK;
            int gr = row0 + mm;
            As[kk][mm] = (gr < N) ? A[(size_t)gr * lda + k0 + kk] : 0.f;
        }
        #pragma unroll
        for (int i = tid; i < BN * BK; i += NTH) {
            int nn = i / BK, kk = i % BK;
            int gc = col0 + nn;
            Ws[kk][nn] = (gc < M) ? W[(size_t)gc * ldw + k0 + kk] : 0.f;
        }
        __syncthreads();

        #pragma unroll
        for (int kk = 0; kk < BK; kk++) {
            float a[TM], b[TN];
            #pragma unroll
            for (int i = 0; i < TM / 4; i++) {
                float4 t = *reinterpret_cast<const float4*>(&As[kk][trow + i * 4]);
                a[i*4+0] = t.x; a[i*4+1] = t.y; a[i*4+2] = t.z; a[i*4+3] = t.w;
            }
            #pragma unroll
            for (int j = 0; j < TN / 4; j++) {
                float4 t = *reinterpret_cast<const float4*>(&Ws[kk][tcol + j * 4]);
                b[j*4+0] = t.x; b[j*4+1] = t.y; b[j*4+2] = t.z; b[j*4+3] = t.w;
            }
            #pragma unroll
            for (int i = 0; i < TM; i++)
                #pragma unroll
                for (int j = 0; j < TN; j++)
                    acc[i][j] += a[i] * b[j];
        }
        __syncthreads();
    }

    #pragma unroll
    for (int i = 0; i < TM; i++) {
        int r = row0 + trow + i;
        if (r >= N) continue;
        #pragma unroll
        for (int j = 0; j < TN; j++) {
            int c = col0 + tcol + j;
            if (c >= M) continue;
            float v = acc[i][j];
            if (bias) v += bias[c];
            if (act == 1) v = leaky_f(v);
            C[(size_t)r * ldc + c] = v;
        }
    }
}

// ---------------------------------------------------------------------------
// Small elementwise / utility kernels
// ---------------------------------------------------------------------------
__global__ void fill_f32(float* p, float v, int n) {
    int i = blockIdx.x * blockDim.x + threadIdx.x;
    if (i < n) p[i] = v;
}
__global__ void fill_u32(unsigned int* p, unsigned int v, int n) {
    int i = blockIdx.x * blockDim.x + threadIdx.x;
    if (i < n) p[i] = v;
}

// cE[m] = sum over edge-dim columns of Wg1 (edge_attr is all ones)
__global__ void comp_cedge(const float* __restrict__ Wg1, float* __restrict__ cE) {
    int m = threadIdx.x;
    if (m < HIDC) {
        float s = 0.f;
        #pragma unroll
        for (int j = 0; j < 25; j++) s += Wg1[(size_t)m * 153 + 128 + j];
        cE[m] = s;
    }
}

// out[row] = dot(A[row,:128], v)
__global__ void rowdot(const float* __restrict__ A, const float* __restrict__ v,
                       float* __restrict__ out, int N)
{
    int gt = blockIdx.x * blockDim.x + threadIdx.x;
    int row = gt >> 5, lane = gt & 31;
    if (row >= N) return;
    const float* a = A + (size_t)row * HIDC;
    float s = 0.f;
    #pragma unroll
    for (int i = 0; i < 4; i++) s += a[lane + i * 32] * v[lane + i * 32];
    #pragma unroll
    for (int off = 16; off; off >>= 1) s += __shfl_xor_sync(0xFFFFFFFFu, s, off);
    if (lane == 0) out[row] = s;
}

// ---------------------------------------------------------------------------
// Edge-segment softmax + scatter (3 passes)
// ---------------------------------------------------------------------------
__global__ void edge_max(const int* __restrict__ src, const int* __restrict__ dst, int E,
                         const float* __restrict__ al, const float* __restrict__ ar,
                         float* __restrict__ m)
{
    int e = blockIdx.x * blockDim.x + threadIdx.x;
    if (e >= E) return;
    float v = leaky_f(al[src[e]] + ar[dst[e]]);
    atomicMaxFloat(&m[dst[e]], v);
}

__global__ void edge_expsum(const int* __restrict__ src, const int* __restrict__ dst, int E,
                            const float* __restrict__ al, const float* __restrict__ ar,
                            const float* __restrict__ m, float* __restrict__ ssum)
{
    int e = blockIdx.x * blockDim.x + threadIdx.x;
    if (e >= E) return;
    int d = dst[e];
    float v = leaky_f(al[src[e]] + ar[d]);
    atomicAdd(&ssum[d], expf(v - m[d]));
}

__global__ void edge_scatter(const int* __restrict__ src, const int* __restrict__ dst, int E,
                             const float* __restrict__ al, const float* __restrict__ ar,
                             const float* __restrict__ m, const float* __restrict__ ssum,
                             const float* __restrict__ Z, float* __restrict__ H)
{
    int gt = blockIdx.x * blockDim.x + threadIdx.x;
    int e = gt >> 5, lane = gt & 31;
    if (e >= E) return;
    int s = src[e], d = dst[e];
    float v = leaky_f(al[s] + ar[d]);
    float w = expf(v - m[d]) / (ssum[d] + 1e-16f);
    float4 z = reinterpret_cast<const float4*>(Z + (size_t)s * HIDC)[lane];
    float* hp = H + (size_t)d * HIDC + lane * 4;
    atomicAdd(hp + 0, z.x * w);
    atomicAdd(hp + 1, z.y * w);
    atomicAdd(hp + 2, z.z * w);
    atomicAdd(hp + 3, z.w * w);
}

__global__ void bias_elu(float* __restrict__ H, const float* __restrict__ b, int total) {
    int i = blockIdx.x * blockDim.x + threadIdx.x;
    if (i >= total) return;
    float v = H[i] + b[i & (HIDC - 1)];
    H[i] = v > 0.f ? v : expm1f(v);
}

// GRU gates + relu, X updated in place (X is the hidden state)
__global__ void gru_gate(const float* __restrict__ GI, const float* __restrict__ GH,
                         float* __restrict__ X, int N)
{
    int i = blockIdx.x * blockDim.x + threadIdx.x;
    if (i >= N * HIDC) return;
    int n = i >> 7, c = i & (HIDC - 1);
    const float* gi = GI + (size_t)n * H3C;
    const float* gh = GH + (size_t)n * H3C;
    float r  = 1.f / (1.f + expf(-(gi[c]       + gh[c])));
    float z  = 1.f / (1.f + expf(-(gi[c + 128] + gh[c + 128])));
    float nn = tanhf(gi[c + 256] + r * gh[c + 256]);
    float o  = (1.f - z) * nn + z * X[i];
    X[i] = fmaxf(o, 0.f);
}

// ---------------------------------------------------------------------------
// Readout kernels (segments = batch, sorted)
// ---------------------------------------------------------------------------
__global__ void node_scatter_sum(const int* __restrict__ batch, const float* __restrict__ X,
                                 float* __restrict__ OUT, int N)
{
    int gt = blockIdx.x * blockDim.x + threadIdx.x;
    int n = gt >> 5, lane = gt & 31;
    if (n >= N) return;
    int b = batch[n];
    float4 v = reinterpret_cast<const float4*>(X + (size_t)n * HIDC)[lane];
    float* op = OUT + (size_t)b * HIDC + lane * 4;
    atomicAdd(op + 0, v.x);
    atomicAdd(op + 1, v.y);
    atomicAdd(op + 2, v.z);
    atomicAdd(op + 3, v.w);
}

__global__ void relu_ip(float* p, int n) {
    int i = blockIdx.x * blockDim.x + threadIdx.x;
    if (i < n) p[i] = fmaxf(p[i], 0.f);
}

__global__ void node_max(const int* __restrict__ batch, int N,
                         const float* __restrict__ asrc, const float* __restrict__ adst,
                         float* __restrict__ m)
{
    int n = blockIdx.x * blockDim.x + threadIdx.x;
    if (n >= N) return;
    int b = batch[n];
    atomicMaxFloat(&m[b], leaky_f(asrc[n] + adst[b]));
}

__global__ void node_expsum(const int* __restrict__ batch, int N,
                            const float* __restrict__ asrc, const float* __restrict__ adst,
                            const float* __restrict__ m, float* __restrict__ ssum)
{
    int n = blockIdx.x * blockDim.x + threadIdx.x;
    if (n >= N) return;
    int b = batch[n];
    atomicAdd(&ssum[b], expf(leaky_f(asrc[n] + adst[b]) - m[b]));
}

__global__ void node_scatter_w(const int* __restrict__ batch, int N,
                               const float* __restrict__ asrc, const float* __restrict__ adst,
                               const float* __restrict__ m, const float* __restrict__ ssum,
                               const float* __restrict__ XT, float* __restrict__ H2)
{
    int gt = blockIdx.x * blockDim.x + threadIdx.x;
    int n = gt >> 5, lane = gt & 31;
    if (n >= N) return;
    int b = batch[n];
    float w = expf(leaky_f(asrc[n] + adst[b]) - m[b]) / (ssum[b] + 1e-16f);
    float4 v = reinterpret_cast<const float4*>(XT + (size_t)n * HIDC)[lane];
    float* hp = H2 + (size_t)b * HIDC + lane * 4;
    atomicAdd(hp + 0, v.x * w);
    atomicAdd(hp + 1, v.y * w);
    atomicAdd(hp + 2, v.z * w);
    atomicAdd(hp + 3, v.w * w);
}

__global__ void final_out(const float* __restrict__ OUT, const float* __restrict__ W2,
                          const float* __restrict__ b2, float* __restrict__ out, int G)
{
    int gt = blockIdx.x * blockDim.x + threadIdx.x;
    int g = gt >> 5, lane = gt & 31;
    if (g >= G) return;
    const float* a = OUT + (size_t)g * HIDC;
    float s = 0.f;
    #pragma unroll
    for (int i = 0; i < 4; i++) s += a[lane + i * 32] * W2[lane + i * 32];
    #pragma unroll
    for (int off = 16; off; off >>= 1) s += __shfl_xor_sync(0xFFFFFFFFu, s, off);
    if (lane == 0) out[g] = s + b2[0];
}

// ---------------------------------------------------------------------------
// Host
// ---------------------------------------------------------------------------
static inline int cdiv(int a, int b) { return (a + b - 1) / b; }

extern "C" void kernel_launch(void* const* d_in, const int* in_sizes, int n_in,
                              void* d_out, int out_size)
{
    const float* x      = (const float*)d_in[0];
    const int*   ei     = (const int*)  d_in[1];
    const int*   batch  = (const int*)  d_in[2];
    const float* W1     = (const float*)d_in[3];
    const float* b1     = (const float*)d_in[4];
    const float* Wg1    = (const float*)d_in[5];
    const float* att_l  = (const float*)d_in[6];
    const float* att_r  = (const float*)d_in[7];
    const float* Wg2    = (const float*)d_in[8];
    const float* bg     = (const float*)d_in[9];
    const float* Wih0   = (const float*)d_in[10];
    const float* Whh0   = (const float*)d_in[11];
    const float* bih0   = (const float*)d_in[12];
    const float* bhh0   = (const float*)d_in[13];
    const float* Wa     = (const float*)d_in[14];
    const float* asrc_a = (const float*)d_in[15];
    const float* adst_a = (const float*)d_in[16];
    const float* ba     = (const float*)d_in[17];
    const float* Wih_a  = (const float*)d_in[18];
    const float* Whh_a  = (const float*)d_in[19];
    const float* bih_a  = (const float*)d_in[20];
    const float* bhh_a  = (const float*)d_in[21];
    const float* Wm     = (const float*)d_in[22];
    const float* asrc_m = (const float*)d_in[23];
    const float* adst_m = (const float*)d_in[24];
    const float* bm     = (const float*)d_in[25];
    const float* Wih_m  = (const float*)d_in[26];
    const float* Whh_m  = (const float*)d_in[27];
    const float* bih_m  = (const float*)d_in[28];
    const float* bhh_m  = (const float*)d_in[29];
    const float* W2     = (const float*)d_in[30];
    const float* b2     = (const float*)d_in[31];
    float* out = (float*)d_out;

    const int N = in_sizes[0] / 64;
    const int E = in_sizes[1] / 2;
    const int G = out_size;   // OUT_CH == 1
    const int* src = ei;
    const int* dst = ei + E;

    float *X, *Z, *H, *GI, *GH, *al, *ar, *m, *sum, *cE;
    float *OUT, *OT, *H2, *GI2, *GH2, *ad;
    cudaGetSymbolAddress((void**)&X,  g_X);
    cudaGetSymbolAddress((void**)&Z,  g_Z);
    cudaGetSymbolAddress((void**)&H,  g_H);
    cudaGetSymbolAddress((void**)&GI, g_GI);
    cudaGetSymbolAddress((void**)&GH, g_GH);
    cudaGetSymbolAddress((void**)&al, g_al);
    cudaGetSymbolAddress((void**)&ar, g_ar);
    cudaGetSymbolAddress((void**)&m,  g_m);
    cudaGetSymbolAddress((void**)&sum,g_sum);
    cudaGetSymbolAddress((void**)&cE, g_cE);
    cudaGetSymbolAddress((void**)&OUT,g_OUT);
    cudaGetSymbolAddress((void**)&OT, g_OT);
    cudaGetSymbolAddress((void**)&H2, g_H2);
    cudaGetSymbolAddress((void**)&GI2,g_GI2);
    cudaGetSymbolAddress((void**)&GH2,g_GH2);
    cudaGetSymbolAddress((void**)&ad, g_ad);

    auto gemmB = [&](const float* A, int lda, const float* W, int ldw,
                     const float* bias, float* C, int n, int mm, int k, int act) {
        dim3 grid(cdiv(mm, 128), cdiv(n, 128));
        gemm_nt<128,128,16,8,8><<<grid, 256>>>(A, lda, W, ldw, bias, C, mm, n, mm, k, act);
    };
    auto gemmS = [&](const float* A, int lda, const float* W, int ldw,
                     const float* bias, float* C, int n, int mm, int k, int act) {
        dim3 grid(cdiv(mm, 64), cdiv(n, 64));
        gemm_nt<64,64,16,4,4><<<grid, 256>>>(A, lda, W, ldw, bias, C, mm, n, mm, k, act);
    };

    const int T256_N   = cdiv(N, 256);
    const int T256_NC  = cdiv(N * HIDC, 256);
    const int T256_E   = cdiv(E, 256);
    const int WARP_E   = cdiv(E * 32, 256);
    const int WARP_N   = cdiv(N * 32, 256);

    // Message-passing phase (softmax over dst segments + weighted scatter of Z)
    auto message_pass = [&](const float* bias_vec) {
        fill_u32<<<T256_N, 256>>>((unsigned int*)m, 0xFF800000u, N);
        fill_f32<<<T256_N, 256>>>(sum, 0.f, N);
        fill_f32<<<T256_NC, 256>>>(H, 0.f, N * HIDC);
        edge_max    <<<T256_E, 256>>>(src, dst, E, al, ar, m);
        edge_expsum <<<T256_E, 256>>>(src, dst, E, al, ar, m, sum);
        edge_scatter<<<WARP_E, 256>>>(src, dst, E, al, ar, m, sum, Z, H);
        bias_elu    <<<T256_NC, 256>>>(H, bias_vec, N * HIDC);
    };
    auto gru_big = [&](const float* Wih, const float* Whh,
                       const float* bih, const float* bhh) {
        gemmB(H, HIDC, Wih, HIDC, bih, GI, N, H3C, HIDC, 0);
        gemmB(X, HIDC, Whh, HIDC, bhh, GH, N, H3C, HIDC, 0);
        gru_gate<<<T256_NC, 256>>>(GI, GH, X, N);
    };

    // ---- Stage 0: x = leaky(x @ W1^T + b1) ----
    comp_cedge<<<1, 128>>>(Wg1, cE);
    gemmB(x, 64, W1, 64, b1, X, N, HIDC, 64, 1);

    // ---- Stage 1: GATEConv + GRU ----
    gemmB(X, HIDC, Wg1, 153, cE, H, N, HIDC, HIDC, 1);      // Y = leaky(x@Wg1a^T + cE)
    rowdot<<<WARP_N, 256>>>(H, att_l, al, N);               // al = Y . att_l
    rowdot<<<WARP_N, 256>>>(X, att_r, ar, N);               // ar = x . att_r
    gemmB(X, HIDC, Wg2, HIDC, nullptr, Z, N, HIDC, HIDC, 0); // Z = x@Wg2^T
    message_pass(bg);
    gru_big(Wih0, Whh0, bih0, bhh0);

    // ---- Stage 2: 2 x (GATConv + GRU) ----
    for (int l = 0; l < 2; l++) {
        gemmB(X, HIDC, Wa + (size_t)l * HIDC * HIDC, HIDC, nullptr, Z, N, HIDC, HIDC, 0);
        rowdot<<<WARP_N, 256>>>(Z, asrc_a + l * HIDC, al, N);
        rowdot<<<WARP_N, 256>>>(Z, adst_a + l * HIDC, ar, N);
        message_pass(ba + l * HIDC);
        gru_big(Wih_a + (size_t)l * H3C * HIDC, Whh_a + (size_t)l * H3C * HIDC,
                bih_a + l * H3C, bhh_a + l * H3C);
    }

    // ---- Stage 3: attentive readout ----
    const int T256_G  = cdiv(G, 256);
    const int T256_GC = cdiv(G * HIDC, 256);
    const int WARP_G  = cdiv(G * 32, 256);

    fill_f32<<<T256_GC, 256>>>(OUT, 0.f, G * HIDC);
    node_scatter_sum<<<WARP_N, 256>>>(batch, X, OUT, N);
    relu_ip<<<T256_GC, 256>>>(OUT, G * HIDC);

    gemmB(X, HIDC, Wm, HIDC, nullptr, Z, N, HIDC, HIDC, 0);  // XT
    rowdot<<<WARP_N, 256>>>(Z, asrc_m, al, N);               // a_src (per node)

    for (int t = 0; t < 3; t++) {
        gemmS(OUT, HIDC, Wm, HIDC, nullptr, OT, G, HIDC, HIDC, 0);
        rowdot<<<WARP_G, 256>>>(OT, adst_m, ad, G);
        fill_u32<<<T256_G, 256>>>((unsigned int*)m, 0xFF800000u, G);
        fill_f32<<<T256_G, 256>>>(sum, 0.f, G);
        fill_f32<<<T256_GC, 256>>>(H2, 0.f, G * HIDC);
        node_max      <<<T256_N, 256>>>(batch, N, al, ad, m);
        node_expsum   <<<T256_N, 256>>>(batch, N, al, ad, m, sum);
        node_scatter_w<<<WARP_N, 256>>>(batch, N, al, ad, m, sum, Z, H2);
        bias_elu      <<<T256_GC, 256>>>(H2, bm, G * HIDC);
        gemmS(H2,  HIDC, Wih_m, HIDC, bih_m, GI2, G, H3C, HIDC, 0);
        gemmS(OUT, HIDC, Whh_m, HIDC, bhh_m, GH2, G, H3C, HIDC, 0);
        gru_gate<<<T256_GC, 256>>>(GI2, GH2, OUT, G);
    }

    final_out<<<WARP_G, 256>>>(OUT, W2, b2, out, G);
}

// round 4
// speedup vs baseline: 1.2169x; 1.2169x over previous
#include <cuda_runtime.h>
#include <math.h>
#include <stdint.h>

// ---------------------------------------------------------------------------
// Problem constants
// ---------------------------------------------------------------------------
#define NMAX   50000
#define EMAX   800000
#define GMAX   1024
#define HIDC   128
#define H3C    384
#define NEGS   0.01f

// ---------------------------------------------------------------------------
// Scratch (device globals; no allocation allowed)
// ---------------------------------------------------------------------------
__device__ float g_X  [(size_t)NMAX * HIDC];
__device__ float g_Z  [(size_t)NMAX * HIDC];
__device__ float g_H  [(size_t)NMAX * HIDC];
__device__ float g_GI [(size_t)NMAX * H3C];
__device__ float g_GH [(size_t)NMAX * H3C];
__device__ float g_al [NMAX];
__device__ float g_ar [NMAX];
__device__ float g_m  [NMAX];
__device__ float g_sum[NMAX];
__device__ float g_cE [HIDC];
__device__ float g_OUT [GMAX * HIDC];
__device__ float g_OT  [GMAX * HIDC];
__device__ float g_H2  [GMAX * HIDC];
__device__ float g_GI2 [GMAX * H3C];
__device__ float g_GH2 [GMAX * H3C];
__device__ float g_ad  [GMAX];

// ---------------------------------------------------------------------------
// Helpers
// ---------------------------------------------------------------------------
__device__ __forceinline__ float leaky_f(float v) { return v >= 0.f ? v : NEGS * v; }

__device__ __forceinline__ void atomicMaxFloat(float* addr, float val) {
    if (val >= 0.f) atomicMax((int*)addr, __float_as_int(val));
    else            atomicMin((unsigned int*)addr, __float_as_uint(val));
}

__device__ __forceinline__ uint32_t f2tf32(float f) {
    uint32_t u; asm("cvt.rna.tf32.f32 %0, %1;" : "=r"(u) : "f"(f)); return u;
}

__device__ __forceinline__ void mma_tf32(float c[4], const uint32_t a[4], const uint32_t b[2]) {
    asm volatile("mma.sync.aligned.m16n8k8.row.col.f32.tf32.tf32.f32 "
        "{%0,%1,%2,%3}, {%4,%5,%6,%7}, {%8,%9}, {%0,%1,%2,%3};"
        : "+f"(c[0]), "+f"(c[1]), "+f"(c[2]), "+f"(c[3])
        : "r"(a[0]), "r"(a[1]), "r"(a[2]), "r"(a[3]), "r"(b[0]), "r"(b[1]));
}

// ---------------------------------------------------------------------------
// Tensor-core NT GEMM (3xTF32 split for fp32-grade accuracy):
//   C[N,M] = act(A[N,K(lda)] * W[M,K(ldw)]^T + bias)
// BM=128, BN=128, BK=16. 256 threads = 8 warps (2 warp-rows x 4 warp-cols),
// each warp computes a 64x32 tile = 4x4 mma tiles.
// Requires: M multiple of 128 (true here: 128 or 384), K multiple of 16.
// ---------------------------------------------------------------------------
#define GBM 128
#define GBN 128
#define GBK 16
#define GBKP 20

__global__ __launch_bounds__(256, 1)
void gemm_tc(const float* __restrict__ A, int lda,
             const float* __restrict__ W, int ldw,
             const float* __restrict__ bias,
             float* __restrict__ C,
             int N, int M, int K, int act)
{
    __shared__ uint32_t sAh[GBM * GBKP], sAl[GBM * GBKP];
    __shared__ uint32_t sBh[GBN * GBKP], sBl[GBN * GBKP];

    const int tid  = threadIdx.x;
    const int lane = tid & 31;
    const int warp = tid >> 5;
    const int gID  = lane >> 2;
    const int tig  = lane & 3;
    const int row0 = blockIdx.y * GBM;
    const int col0 = blockIdx.x * GBN;
    const int warpM = (warp >> 2) * 64;
    const int warpN = (warp & 3) * 32;

    float c[4][4][4];
    #pragma unroll
    for (int i = 0; i < 4; i++)
        #pragma unroll
        for (int j = 0; j < 4; j++)
            #pragma unroll
            for (int q = 0; q < 4; q++) c[i][j][q] = 0.f;

    for (int k0 = 0; k0 < K; k0 += GBK) {
        __syncthreads();
        #pragma unroll 4
        for (int i = tid; i < GBM * GBK; i += 256) {
            int mm = i >> 4, kk = i & 15;
            int gr = row0 + mm;
            float v = (gr < N) ? A[(size_t)gr * lda + k0 + kk] : 0.f;
            uint32_t hi = f2tf32(v);
            uint32_t lo = f2tf32(v - __uint_as_float(hi));
            sAh[mm * GBKP + kk] = hi;
            sAl[mm * GBKP + kk] = lo;
        }
        #pragma unroll 4
        for (int i = tid; i < GBN * GBK; i += 256) {
            int nn = i >> 4, kk = i & 15;
            int gc = col0 + nn;
            float v = (gc < M) ? W[(size_t)gc * ldw + k0 + kk] : 0.f;
            uint32_t hi = f2tf32(v);
            uint32_t lo = f2tf32(v - __uint_as_float(hi));
            sBh[nn * GBKP + kk] = hi;
            sBl[nn * GBKP + kk] = lo;
        }
        __syncthreads();

        #pragma unroll
        for (int ks = 0; ks < GBK; ks += 8) {
            uint32_t ah[4][4], alo[4][4], bh[4][2], blo[4][2];
            #pragma unroll
            for (int i = 0; i < 4; i++) {
                int r0 = (warpM + i * 16 + gID) * GBKP + ks + tig;
                int r1 = (warpM + i * 16 + 8 + gID) * GBKP + ks + tig;
                ah[i][0] = sAh[r0];     ah[i][1] = sAh[r1];
                ah[i][2] = sAh[r0 + 4]; ah[i][3] = sAh[r1 + 4];
                alo[i][0] = sAl[r0];     alo[i][1] = sAl[r1];
                alo[i][2] = sAl[r0 + 4]; alo[i][3] = sAl[r1 + 4];
            }
            #pragma unroll
            for (int j = 0; j < 4; j++) {
                int q0 = (warpN + j * 8 + gID) * GBKP + ks + tig;
                bh[j][0] = sBh[q0]; bh[j][1] = sBh[q0 + 4];
                blo[j][0] = sBl[q0]; blo[j][1] = sBl[q0 + 4];
            }
            #pragma unroll
            for (int i = 0; i < 4; i++)
                #pragma unroll
                for (int j = 0; j < 4; j++) {
                    mma_tf32(c[i][j], alo[i], bh[j]);
                    mma_tf32(c[i][j], ah[i], blo[j]);
                    mma_tf32(c[i][j], ah[i], bh[j]);
                }
        }
    }

    // Epilogue
    #pragma unroll
    for (int i = 0; i < 4; i++) {
        int r_lo = row0 + warpM + i * 16 + gID;
        int r_hi = r_lo + 8;
        #pragma unroll
        for (int j = 0; j < 4; j++) {
            int cc = col0 + warpN + j * 8 + tig * 2;
            float b0 = bias ? bias[cc] : 0.f;
            float b1 = bias ? bias[cc + 1] : 0.f;
            float v0 = c[i][j][0] + b0, v1 = c[i][j][1] + b1;
            float v2 = c[i][j][2] + b0, v3 = c[i][j][3] + b1;
            if (act == 1) { v0 = leaky_f(v0); v1 = leaky_f(v1); v2 = leaky_f(v2); v3 = leaky_f(v3); }
            if (r_lo < N) {
                C[(size_t)r_lo * M + cc]     = v0;
                C[(size_t)r_lo * M + cc + 1] = v1;
            }
            if (r_hi < N) {
                C[(size_t)r_hi * M + cc]     = v2;
                C[(size_t)r_hi * M + cc + 1] = v3;
            }
        }
    }
}

// ---------------------------------------------------------------------------
// Small elementwise / utility kernels
// ---------------------------------------------------------------------------
__global__ void fill_f32(float* p, float v, int n) {
    int i = blockIdx.x * blockDim.x + threadIdx.x;
    if (i < n) p[i] = v;
}
__global__ void fill_u32(unsigned int* p, unsigned int v, int n) {
    int i = blockIdx.x * blockDim.x + threadIdx.x;
    if (i < n) p[i] = v;
}

__global__ void comp_cedge(const float* __restrict__ Wg1, float* __restrict__ cE) {
    int m = threadIdx.x;
    if (m < HIDC) {
        float s = 0.f;
        #pragma unroll
        for (int j = 0; j < 25; j++) s += Wg1[(size_t)m * 153 + 128 + j];
        cE[m] = s;
    }
}

__global__ void rowdot(const float* __restrict__ A, const float* __restrict__ v,
                       float* __restrict__ out, int N)
{
    int gt = blockIdx.x * blockDim.x + threadIdx.x;
    int row = gt >> 5, lane = gt & 31;
    if (row >= N) return;
    const float* a = A + (size_t)row * HIDC;
    float s = 0.f;
    #pragma unroll
    for (int i = 0; i < 4; i++) s += a[lane + i * 32] * v[lane + i * 32];
    #pragma unroll
    for (int off = 16; off; off >>= 1) s += __shfl_xor_sync(0xFFFFFFFFu, s, off);
    if (lane == 0) out[row] = s;
}

// ---------------------------------------------------------------------------
// Edge-segment softmax + scatter (2 passes: max, then fused exp-scatter)
// Normalization by segment sum is deferred to the bias/ELU epilogue.
// ---------------------------------------------------------------------------
__global__ void edge_max(const int* __restrict__ src, const int* __restrict__ dst, int E,
                         const float* __restrict__ al, const float* __restrict__ ar,
                         float* __restrict__ m)
{
    int e = blockIdx.x * blockDim.x + threadIdx.x;
    if (e >= E) return;
    float v = leaky_f(al[src[e]] + ar[dst[e]]);
    atomicMaxFloat(&m[dst[e]], v);
}

__global__ void edge_scatter_f(const int* __restrict__ src, const int* __restrict__ dst, int E,
                               const float* __restrict__ al, const float* __restrict__ ar,
                               const float* __restrict__ m, float* __restrict__ ssum,
                               const float* __restrict__ Z, float* __restrict__ H)
{
    int gt = blockIdx.x * blockDim.x + threadIdx.x;
    int e = gt >> 5, lane = gt & 31;
    if (e >= E) return;
    int s = src[e], d = dst[e];
    float v = leaky_f(al[s] + ar[d]);
    float w = expf(v - m[d]);
    if (lane == 0) atomicAdd(&ssum[d], w);
    float4 z = reinterpret_cast<const float4*>(Z + (size_t)s * HIDC)[lane];
    float* hp = H + (size_t)d * HIDC + lane * 4;
    atomicAdd(hp + 0, z.x * w);
    atomicAdd(hp + 1, z.y * w);
    atomicAdd(hp + 2, z.z * w);
    atomicAdd(hp + 3, z.w * w);
}

// H[i] = elu(H[i]/(sum[row]+1e-16) + b[col])
__global__ void bias_elu_div(float* __restrict__ H, const float* __restrict__ ssum,
                             const float* __restrict__ b, int total) {
    int i = blockIdx.x * blockDim.x + threadIdx.x;
    if (i >= total) return;
    int n = i >> 7, c = i & (HIDC - 1);
    float v = H[i] / (ssum[n] + 1e-16f) + b[c];
    H[i] = v > 0.f ? v : expm1f(v);
}

__global__ void gru_gate(const float* __restrict__ GI, const float* __restrict__ GH,
                         float* __restrict__ X, int N)
{
    int i = blockIdx.x * blockDim.x + threadIdx.x;
    if (i >= N * HIDC) return;
    int n = i >> 7, c = i & (HIDC - 1);
    const float* gi = GI + (size_t)n * H3C;
    const float* gh = GH + (size_t)n * H3C;
    float r  = 1.f / (1.f + expf(-(gi[c]       + gh[c])));
    float z  = 1.f / (1.f + expf(-(gi[c + 128] + gh[c + 128])));
    float nn = tanhf(gi[c + 256] + r * gh[c + 256]);
    float o  = (1.f - z) * nn + z * X[i];
    X[i] = fmaxf(o, 0.f);
}

// ---------------------------------------------------------------------------
// Readout kernels
// ---------------------------------------------------------------------------
__global__ void node_scatter_sum(const int* __restrict__ batch, const float* __restrict__ X,
                                 float* __restrict__ OUT, int N)
{
    int gt = blockIdx.x * blockDim.x + threadIdx.x;
    int n = gt >> 5, lane = gt & 31;
    if (n >= N) return;
    int b = batch[n];
    float4 v = reinterpret_cast<const float4*>(X + (size_t)n * HIDC)[lane];
    float* op = OUT + (size_t)b * HIDC + lane * 4;
    atomicAdd(op + 0, v.x);
    atomicAdd(op + 1, v.y);
    atomicAdd(op + 2, v.z);
    atomicAdd(op + 3, v.w);
}

__global__ void relu_ip(float* p, int n) {
    int i = blockIdx.x * blockDim.x + threadIdx.x;
    if (i < n) p[i] = fmaxf(p[i], 0.f);
}

__global__ void node_max(const int* __restrict__ batch, int N,
                         const float* __restrict__ asrc, const float* __restrict__ adst,
                         float* __restrict__ m)
{
    int n = blockIdx.x * blockDim.x + threadIdx.x;
    if (n >= N) return;
    int b = batch[n];
    atomicMaxFloat(&m[b], leaky_f(asrc[n] + adst[b]));
}

__global__ void node_scatter_f(const int* __restrict__ batch, int N,
                               const float* __restrict__ asrc, const float* __restrict__ adst,
                               const float* __restrict__ m, float* __restrict__ ssum,
                               const float* __restrict__ XT, float* __restrict__ H2)
{
    int gt = blockIdx.x * blockDim.x + threadIdx.x;
    int n = gt >> 5, lane = gt & 31;
    if (n >= N) return;
    int b = batch[n];
    float w = expf(leaky_f(asrc[n] + adst[b]) - m[b]);
    if (lane == 0) atomicAdd(&ssum[b], w);
    float4 v = reinterpret_cast<const float4*>(XT + (size_t)n * HIDC)[lane];
    float* hp = H2 + (size_t)b * HIDC + lane * 4;
    atomicAdd(hp + 0, v.x * w);
    atomicAdd(hp + 1, v.y * w);
    atomicAdd(hp + 2, v.z * w);
    atomicAdd(hp + 3, v.w * w);
}

__global__ void final_out(const float* __restrict__ OUT, const float* __restrict__ W2,
                          const float* __restrict__ b2, float* __restrict__ out, int G)
{
    int gt = blockIdx.x * blockDim.x + threadIdx.x;
    int g = gt >> 5, lane = gt & 31;
    if (g >= G) return;
    const float* a = OUT + (size_t)g * HIDC;
    float s = 0.f;
    #pragma unroll
    for (int i = 0; i < 4; i++) s += a[lane + i * 32] * W2[lane + i * 32];
    #pragma unroll
    for (int off = 16; off; off >>= 1) s += __shfl_xor_sync(0xFFFFFFFFu, s, off);
    if (lane == 0) out[g] = s + b2[0];
}

// ---------------------------------------------------------------------------
// Host
// ---------------------------------------------------------------------------
static inline int cdiv(int a, int b) { return (a + b - 1) / b; }

extern "C" void kernel_launch(void* const* d_in, const int* in_sizes, int n_in,
                              void* d_out, int out_size)
{
    const float* x      = (const float*)d_in[0];
    const int*   ei     = (const int*)  d_in[1];
    const int*   batch  = (const int*)  d_in[2];
    const float* W1     = (const float*)d_in[3];
    const float* b1     = (const float*)d_in[4];
    const float* Wg1    = (const float*)d_in[5];
    const float* att_l  = (const float*)d_in[6];
    const float* att_r  = (const float*)d_in[7];
    const float* Wg2    = (const float*)d_in[8];
    const float* bg     = (const float*)d_in[9];
    const float* Wih0   = (const float*)d_in[10];
    const float* Whh0   = (const float*)d_in[11];
    const float* bih0   = (const float*)d_in[12];
    const float* bhh0   = (const float*)d_in[13];
    const float* Wa     = (const float*)d_in[14];
    const float* asrc_a = (const float*)d_in[15];
    const float* adst_a = (const float*)d_in[16];
    const float* ba     = (const float*)d_in[17];
    const float* Wih_a  = (const float*)d_in[18];
    const float* Whh_a  = (const float*)d_in[19];
    const float* bih_a  = (const float*)d_in[20];
    const float* bhh_a  = (const float*)d_in[21];
    const float* Wm     = (const float*)d_in[22];
    const float* asrc_m = (const float*)d_in[23];
    const float* adst_m = (const float*)d_in[24];
    const float* bm     = (const float*)d_in[25];
    const float* Wih_m  = (const float*)d_in[26];
    const float* Whh_m  = (const float*)d_in[27];
    const float* bih_m  = (const float*)d_in[28];
    const float* bhh_m  = (const float*)d_in[29];
    const float* W2     = (const float*)d_in[30];
    const float* b2     = (const float*)d_in[31];
    float* out = (float*)d_out;

    const int N = in_sizes[0] / 64;
    const int E = in_sizes[1] / 2;
    const int G = out_size;
    const int* src = ei;
    const int* dst = ei + E;

    float *X, *Z, *H, *GI, *GH, *al, *ar, *m, *sum, *cE;
    float *OUT, *OT, *H2, *GI2, *GH2, *ad;
    cudaGetSymbolAddress((void**)&X,  g_X);
    cudaGetSymbolAddress((void**)&Z,  g_Z);
    cudaGetSymbolAddress((void**)&H,  g_H);
    cudaGetSymbolAddress((void**)&GI, g_GI);
    cudaGetSymbolAddress((void**)&GH, g_GH);
    cudaGetSymbolAddress((void**)&al, g_al);
    cudaGetSymbolAddress((void**)&ar, g_ar);
    cudaGetSymbolAddress((void**)&m,  g_m);
    cudaGetSymbolAddress((void**)&sum,g_sum);
    cudaGetSymbolAddress((void**)&cE, g_cE);
    cudaGetSymbolAddress((void**)&OUT,g_OUT);
    cudaGetSymbolAddress((void**)&OT, g_OT);
    cudaGetSymbolAddress((void**)&H2, g_H2);
    cudaGetSymbolAddress((void**)&GI2,g_GI2);
    cudaGetSymbolAddress((void**)&GH2,g_GH2);
    cudaGetSymbolAddress((void**)&ad, g_ad);

    // Tensor-core GEMM launcher: C[N,M] = act(A*W^T + bias), M % 128 == 0
    auto gemm = [&](const float* A, int lda, const float* W, int ldw,
                    const float* bias, float* C, int n, int mm, int k, int act) {
        dim3 grid(mm / 128, cdiv(n, 128));
        gemm_tc<<<grid, 256>>>(A, lda, W, ldw, bias, C, n, mm, k, act);
    };

    const int T256_N   = cdiv(N, 256);
    const int T256_NC  = cdiv(N * HIDC, 256);
    const int T256_E   = cdiv(E, 256);
    const int WARP_E   = cdiv(E * 32, 256);
    const int WARP_N   = cdiv(N * 32, 256);

    auto message_pass = [&](const float* bias_vec) {
        fill_u32<<<T256_N, 256>>>((unsigned int*)m, 0xFF800000u, N);
        fill_f32<<<T256_N, 256>>>(sum, 0.f, N);
        fill_f32<<<T256_NC, 256>>>(H, 0.f, N * HIDC);
        edge_max      <<<T256_E, 256>>>(src, dst, E, al, ar, m);
        edge_scatter_f<<<WARP_E, 256>>>(src, dst, E, al, ar, m, sum, Z, H);
        bias_elu_div  <<<T256_NC, 256>>>(H, sum, bias_vec, N * HIDC);
    };
    auto gru_big = [&](const float* Wih, const float* Whh,
                       const float* bih, const float* bhh) {
        gemm(H, HIDC, Wih, HIDC, bih, GI, N, H3C, HIDC, 0);
        gemm(X, HIDC, Whh, HIDC, bhh, GH, N, H3C, HIDC, 0);
        gru_gate<<<T256_NC, 256>>>(GI, GH, X, N);
    };

    // ---- Stage 0: x = leaky(x @ W1^T + b1) ----
    comp_cedge<<<1, 128>>>(Wg1, cE);
    gemm(x, 64, W1, 64, b1, X, N, HIDC, 64, 1);

    // ---- Stage 1: GATEConv + GRU ----
    gemm(X, HIDC, Wg1, 153, cE, H, N, HIDC, HIDC, 1);
    rowdot<<<WARP_N, 256>>>(H, att_l, al, N);
    rowdot<<<WARP_N, 256>>>(X, att_r, ar, N);
    gemm(X, HIDC, Wg2, HIDC, nullptr, Z, N, HIDC, HIDC, 0);
    message_pass(bg);
    gru_big(Wih0, Whh0, bih0, bhh0);

    // ---- Stage 2: 2 x (GATConv + GRU) ----
    for (int l = 0; l < 2; l++) {
        gemm(X, HIDC, Wa + (size_t)l * HIDC * HIDC, HIDC, nullptr, Z, N, HIDC, HIDC, 0);
        rowdot<<<WARP_N, 256>>>(Z, asrc_a + l * HIDC, al, N);
        rowdot<<<WARP_N, 256>>>(Z, adst_a + l * HIDC, ar, N);
        message_pass(ba + l * HIDC);
        gru_big(Wih_a + (size_t)l * H3C * HIDC, Whh_a + (size_t)l * H3C * HIDC,
                bih_a + l * H3C, bhh_a + l * H3C);
    }

    // ---- Stage 3: attentive readout ----
    const int T256_G  = cdiv(G, 256);
    const int T256_GC = cdiv(G * HIDC, 256);
    const int WARP_G  = cdiv(G * 32, 256);

    fill_f32<<<T256_GC, 256>>>(OUT, 0.f, G * HIDC);
    node_scatter_sum<<<WARP_N, 256>>>(batch, X, OUT, N);
    relu_ip<<<T256_GC, 256>>>(OUT, G * HIDC);

    gemm(X, HIDC, Wm, HIDC, nullptr, Z, N, HIDC, HIDC, 0);
    rowdot<<<WARP_N, 256>>>(Z, asrc_m, al, N);

    for (int t = 0; t < 3; t++) {
        gemm(OUT, HIDC, Wm, HIDC, nullptr, OT, G, HIDC, HIDC, 0);
        rowdot<<<WARP_G, 256>>>(OT, adst_m, ad, G);
        fill_u32<<<T256_G, 256>>>((unsigned int*)m, 0xFF800000u, G);
        fill_f32<<<T256_G, 256>>>(sum, 0.f, G);
        fill_f32<<<T256_GC, 256>>>(H2, 0.f, G * HIDC);
        node_max      <<<T256_N, 256>>>(batch, N, al, ad, m);
        node_scatter_f<<<WARP_N, 256>>>(batch, N, al, ad, m, sum, Z, H2);
        bias_elu_div  <<<T256_GC, 256>>>(H2, sum, bm, G * HIDC);
        gemm(H2,  HIDC, Wih_m, HIDC, bih_m, GI2, G, H3C, HIDC, 0);
        gemm(OUT, HIDC, Whh_m, HIDC, bhh_m, GH2, G, H3C, HIDC, 0);
        gru_gate<<<T256_GC, 256>>>(GI2, GH2, OUT, G);
    }

    final_out<<<WARP_G, 256>>>(OUT, W2, b2, out, G);
}

// round 5
// speedup vs baseline: 2.2685x; 1.8642x over previous
#include <cuda_runtime.h>
#include <cuda_bf16.h>
#include <math.h>
#include <stdint.h>

// ---------------------------------------------------------------------------
// Problem constants
// ---------------------------------------------------------------------------
#define NMAX   50000
#define EMAX   800000
#define GMAX   1024
#define HIDC   128
#define H3C    384
#define NEGS   0.01f

// ---------------------------------------------------------------------------
// Scratch (device globals; no allocation allowed)
// ---------------------------------------------------------------------------
__device__ float g_X  [(size_t)NMAX * HIDC];
__device__ float g_Z  [(size_t)NMAX * HIDC];
__device__ float g_H  [(size_t)NMAX * HIDC];
__device__ float g_GI [(size_t)NMAX * H3C];
__device__ float g_GH [(size_t)NMAX * H3C];
__device__ float g_al [NMAX];
__device__ float g_ar [NMAX];
__device__ float g_m  [NMAX];
__device__ float g_sum[NMAX];
__device__ float g_cE [HIDC];
__device__ float g_Wg1p[HIDC * HIDC];          // packed Wg1[:, :128]
__device__ float g_OUT [GMAX * HIDC];
__device__ float g_OT  [GMAX * HIDC];
__device__ float g_H2  [GMAX * HIDC];
__device__ float g_GI2 [GMAX * H3C];
__device__ float g_GH2 [GMAX * H3C];
__device__ float g_ad  [GMAX];

// ---------------------------------------------------------------------------
// Helpers
// ---------------------------------------------------------------------------
__device__ __forceinline__ float leaky_f(float v) { return v >= 0.f ? v : NEGS * v; }

__device__ __forceinline__ void atomicMaxFloat(float* addr, float val) {
    if (val >= 0.f) atomicMax((int*)addr, __float_as_int(val));
    else            atomicMin((unsigned int*)addr, __float_as_uint(val));
}

__device__ __forceinline__ void redv4(float* p, float a, float b, float c, float d) {
    asm volatile("red.global.add.v4.f32 [%0], {%1,%2,%3,%4};"
                 :: "l"(p), "f"(a), "f"(b), "f"(c), "f"(d) : "memory");
}

// Split a pair of floats into packed bf16 hi and lo parts
__device__ __forceinline__ void split2(float a, float b, uint32_t& hi, uint32_t& lo) {
    __nv_bfloat16 ah = __float2bfloat16_rn(a);
    __nv_bfloat16 bh = __float2bfloat16_rn(b);
    __nv_bfloat162 h; h.x = ah; h.y = bh;
    hi = *reinterpret_cast<uint32_t*>(&h);
    __nv_bfloat162 l;
    l.x = __float2bfloat16_rn(a - __bfloat162float(ah));
    l.y = __float2bfloat16_rn(b - __bfloat162float(bh));
    lo = *reinterpret_cast<uint32_t*>(&l);
}

__device__ __forceinline__ void mma_bf16(float c[4], const uint32_t a[4], const uint32_t b[2]) {
    asm volatile("mma.sync.aligned.m16n8k16.row.col.f32.bf16.bf16.f32 "
        "{%0,%1,%2,%3}, {%4,%5,%6,%7}, {%8,%9}, {%0,%1,%2,%3};"
        : "+f"(c[0]), "+f"(c[1]), "+f"(c[2]), "+f"(c[3])
        : "r"(a[0]), "r"(a[1]), "r"(a[2]), "r"(a[3]), "r"(b[0]), "r"(b[1]));
}

// ---------------------------------------------------------------------------
// bf16 2-way-split tensor-core NT GEMM:
//   C[N,M] = act(A[N,K(lda)] * W[M,K(ldw)]^T + bias)
// BM=128, BN=128, BK=32. 256 threads = 8 warps (2x4), warp tile 64x32.
// Requires: M % 128 == 0, K % 32 == 0, lda/ldw % 4 == 0 (float4 loads).
// ---------------------------------------------------------------------------
#define KP 17   // packed-pair row stride (16 pairs + 1 pad)

__global__ __launch_bounds__(256)
void gemm_bf(const float* __restrict__ A, int lda,
             const float* __restrict__ W, int ldw,
             const float* __restrict__ bias,
             float* __restrict__ C,
             int N, int M, int K, int act)
{
    __shared__ uint32_t sAh[128 * KP], sAl[128 * KP];
    __shared__ uint32_t sBh[128 * KP], sBl[128 * KP];

    const int tid  = threadIdx.x;
    const int lane = tid & 31;
    const int warp = tid >> 5;
    const int gID  = lane >> 2;
    const int tig  = lane & 3;
    const int row0 = blockIdx.y * 128;
    const int col0 = blockIdx.x * 128;
    const int warpM = (warp >> 2) * 64;
    const int warpN = (warp & 3) * 32;

    float c[4][4][4];
    #pragma unroll
    for (int i = 0; i < 4; i++)
        #pragma unroll
        for (int j = 0; j < 4; j++)
            #pragma unroll
            for (int q = 0; q < 4; q++) c[i][j][q] = 0.f;

    const int nkt = K / 32;
    float4 ra[4], rb[4];

    auto loadA = [&](float4 r[4], int k0) {
        #pragma unroll
        for (int s = 0; s < 4; s++) {
            int idx = tid + s * 256;
            int row = idx >> 3, q = idx & 7;
            int gr = row0 + row;
            r[s] = (gr < N) ? *reinterpret_cast<const float4*>(A + (size_t)gr * lda + k0 + q * 4)
                            : make_float4(0.f, 0.f, 0.f, 0.f);
        }
    };
    auto loadB = [&](float4 r[4], int k0) {
        #pragma unroll
        for (int s = 0; s < 4; s++) {
            int idx = tid + s * 256;
            int row = idx >> 3, q = idx & 7;
            int gc = col0 + row;
            r[s] = (gc < M) ? *reinterpret_cast<const float4*>(W + (size_t)gc * ldw + k0 + q * 4)
                            : make_float4(0.f, 0.f, 0.f, 0.f);
        }
    };

    loadA(ra, 0);
    loadB(rb, 0);

    for (int kt = 0; kt < nkt; kt++) {
        // store prefetched tile (convert f32 -> bf16 hi/lo packed pairs)
        #pragma unroll
        for (int s = 0; s < 4; s++) {
            int idx = tid + s * 256;
            int row = idx >> 3, q = idx & 7;
            uint32_t h0, l0, h1, l1;
            split2(ra[s].x, ra[s].y, h0, l0);
            split2(ra[s].z, ra[s].w, h1, l1);
            sAh[row * KP + q * 2]     = h0;
            sAh[row * KP + q * 2 + 1] = h1;
            sAl[row * KP + q * 2]     = l0;
            sAl[row * KP + q * 2 + 1] = l1;
            split2(rb[s].x, rb[s].y, h0, l0);
            split2(rb[s].z, rb[s].w, h1, l1);
            sBh[row * KP + q * 2]     = h0;
            sBh[row * KP + q * 2 + 1] = h1;
            sBl[row * KP + q * 2]     = l0;
            sBl[row * KP + q * 2 + 1] = l1;
        }
        __syncthreads();

        if (kt + 1 < nkt) {
            loadA(ra, (kt + 1) * 32);
            loadB(rb, (kt + 1) * 32);
        }

        #pragma unroll
        for (int s2 = 0; s2 < 2; s2++) {
            const int pb = s2 * 8;
            uint32_t ah[4][4], al4[4][4];
            #pragma unroll
            for (int i = 0; i < 4; i++) {
                int rA  = (warpM + i * 16 + gID) * KP + pb + tig;
                int rA8 = rA + 8 * KP;
                ah[i][0] = sAh[rA];      ah[i][1] = sAh[rA8];
                ah[i][2] = sAh[rA + 4];  ah[i][3] = sAh[rA8 + 4];
                al4[i][0] = sAl[rA];     al4[i][1] = sAl[rA8];
                al4[i][2] = sAl[rA + 4]; al4[i][3] = sAl[rA8 + 4];
            }
            #pragma unroll
            for (int j = 0; j < 4; j++) {
                int nb = (warpN + j * 8 + gID) * KP + pb + tig;
                uint32_t bh[2] = { sBh[nb], sBh[nb + 4] };
                uint32_t bl[2] = { sBl[nb], sBl[nb + 4] };
                #pragma unroll
                for (int i = 0; i < 4; i++) {
                    mma_bf16(c[i][j], ah[i],  bh);
                    mma_bf16(c[i][j], al4[i], bh);
                    mma_bf16(c[i][j], ah[i],  bl);
                }
            }
        }
        __syncthreads();
    }

    // Epilogue
    #pragma unroll
    for (int i = 0; i < 4; i++) {
        int r_lo = row0 + warpM + i * 16 + gID;
        int r_hi = r_lo + 8;
        #pragma unroll
        for (int j = 0; j < 4; j++) {
            int cc = col0 + warpN + j * 8 + tig * 2;
            float b0 = bias ? bias[cc] : 0.f;
            float b1 = bias ? bias[cc + 1] : 0.f;
            float v0 = c[i][j][0] + b0, v1 = c[i][j][1] + b1;
            float v2 = c[i][j][2] + b0, v3 = c[i][j][3] + b1;
            if (act == 1) { v0 = leaky_f(v0); v1 = leaky_f(v1); v2 = leaky_f(v2); v3 = leaky_f(v3); }
            if (r_lo < N) {
                C[(size_t)r_lo * M + cc]     = v0;
                C[(size_t)r_lo * M + cc + 1] = v1;
            }
            if (r_hi < N) {
                C[(size_t)r_hi * M + cc]     = v2;
                C[(size_t)r_hi * M + cc + 1] = v3;
            }
        }
    }
}

// ---------------------------------------------------------------------------
// Small elementwise / utility kernels
// ---------------------------------------------------------------------------
__global__ void fill_f32(float* p, float v, int n) {
    int i = blockIdx.x * blockDim.x + threadIdx.x;
    if (i < n) p[i] = v;
}
__global__ void fill_u32(unsigned int* p, unsigned int v, int n) {
    int i = blockIdx.x * blockDim.x + threadIdx.x;
    if (i < n) p[i] = v;
}

__global__ void comp_cedge(const float* __restrict__ Wg1, float* __restrict__ cE) {
    int m = threadIdx.x;
    if (m < HIDC) {
        float s = 0.f;
        #pragma unroll
        for (int j = 0; j < 25; j++) s += Wg1[(size_t)m * 153 + 128 + j];
        cE[m] = s;
    }
}

__global__ void pack_wg1(const float* __restrict__ Wg1, float* __restrict__ out) {
    int i = blockIdx.x * blockDim.x + threadIdx.x;
    if (i < HIDC * HIDC) {
        int r = i >> 7, c = i & 127;
        out[i] = Wg1[(size_t)r * 153 + c];
    }
}

__global__ void rowdot(const float* __restrict__ A, const float* __restrict__ v,
                       float* __restrict__ out, int N)
{
    int gt = blockIdx.x * blockDim.x + threadIdx.x;
    int row = gt >> 5, lane = gt & 31;
    if (row >= N) return;
    const float* a = A + (size_t)row * HIDC;
    float s = 0.f;
    #pragma unroll
    for (int i = 0; i < 4; i++) s += a[lane + i * 32] * v[lane + i * 32];
    #pragma unroll
    for (int off = 16; off; off >>= 1) s += __shfl_xor_sync(0xFFFFFFFFu, s, off);
    if (lane == 0) out[row] = s;
}

// ---------------------------------------------------------------------------
// Edge-segment softmax + scatter (2 passes; normalization deferred)
// ---------------------------------------------------------------------------
__global__ void edge_max(const int* __restrict__ src, const int* __restrict__ dst, int E,
                         const float* __restrict__ al, const float* __restrict__ ar,
                         float* __restrict__ m)
{
    int e = blockIdx.x * blockDim.x + threadIdx.x;
    if (e >= E) return;
    float v = leaky_f(al[src[e]] + ar[dst[e]]);
    atomicMaxFloat(&m[dst[e]], v);
}

__global__ void edge_scatter_f(const int* __restrict__ src, const int* __restrict__ dst, int E,
                               const float* __restrict__ al, const float* __restrict__ ar,
                               const float* __restrict__ m, float* __restrict__ ssum,
                               const float* __restrict__ Z, float* __restrict__ H)
{
    int gt = blockIdx.x * blockDim.x + threadIdx.x;
    int e = gt >> 5, lane = gt & 31;
    if (e >= E) return;
    int s = src[e], d = dst[e];
    float v = leaky_f(al[s] + ar[d]);
    float w = expf(v - m[d]);
    if (lane == 0) atomicAdd(&ssum[d], w);
    float4 z = reinterpret_cast<const float4*>(Z + (size_t)s * HIDC)[lane];
    redv4(H + (size_t)d * HIDC + lane * 4, z.x * w, z.y * w, z.z * w, z.w * w);
}

// H[i] = elu(H[i]/(sum[row]+1e-16) + b[col])
__global__ void bias_elu_div(float* __restrict__ H, const float* __restrict__ ssum,
                             const float* __restrict__ b, int total) {
    int i = blockIdx.x * blockDim.x + threadIdx.x;
    if (i >= total) return;
    int n = i >> 7, c = i & (HIDC - 1);
    float v = H[i] / (ssum[n] + 1e-16f) + b[c];
    H[i] = v > 0.f ? v : expm1f(v);
}

__global__ void gru_gate(const float* __restrict__ GI, const float* __restrict__ GH,
                         float* __restrict__ X, int N)
{
    int i = blockIdx.x * blockDim.x + threadIdx.x;
    if (i >= N * HIDC) return;
    int n = i >> 7, c = i & (HIDC - 1);
    const float* gi = GI + (size_t)n * H3C;
    const float* gh = GH + (size_t)n * H3C;
    float r  = 1.f / (1.f + expf(-(gi[c]       + gh[c])));
    float z  = 1.f / (1.f + expf(-(gi[c + 128] + gh[c + 128])));
    float nn = tanhf(gi[c + 256] + r * gh[c + 256]);
    float o  = (1.f - z) * nn + z * X[i];
    X[i] = fmaxf(o, 0.f);
}

// ---------------------------------------------------------------------------
// Readout kernels
// ---------------------------------------------------------------------------
__global__ void node_scatter_sum(const int* __restrict__ batch, const float* __restrict__ X,
                                 float* __restrict__ OUT, int N)
{
    int gt = blockIdx.x * blockDim.x + threadIdx.x;
    int n = gt >> 5, lane = gt & 31;
    if (n >= N) return;
    int b = batch[n];
    float4 v = reinterpret_cast<const float4*>(X + (size_t)n * HIDC)[lane];
    redv4(OUT + (size_t)b * HIDC + lane * 4, v.x, v.y, v.z, v.w);
}

__global__ void relu_ip(float* p, int n) {
    int i = blockIdx.x * blockDim.x + threadIdx.x;
    if (i < n) p[i] = fmaxf(p[i], 0.f);
}

__global__ void node_max(const int* __restrict__ batch, int N,
                         const float* __restrict__ asrc, const float* __restrict__ adst,
                         float* __restrict__ m)
{
    int n = blockIdx.x * blockDim.x + threadIdx.x;
    if (n >= N) return;
    int b = batch[n];
    atomicMaxFloat(&m[b], leaky_f(asrc[n] + adst[b]));
}

__global__ void node_scatter_f(const int* __restrict__ batch, int N,
                               const float* __restrict__ asrc, const float* __restrict__ adst,
                               const float* __restrict__ m, float* __restrict__ ssum,
                               const float* __restrict__ XT, float* __restrict__ H2)
{
    int gt = blockIdx.x * blockDim.x + threadIdx.x;
    int n = gt >> 5, lane = gt & 31;
    if (n >= N) return;
    int b = batch[n];
    float w = expf(leaky_f(asrc[n] + adst[b]) - m[b]);
    if (lane == 0) atomicAdd(&ssum[b], w);
    float4 v = reinterpret_cast<const float4*>(XT + (size_t)n * HIDC)[lane];
    redv4(H2 + (size_t)b * HIDC + lane * 4, v.x * w, v.y * w, v.z * w, v.w * w);
}

__global__ void final_out(const float* __restrict__ OUT, const float* __restrict__ W2,
                          const float* __restrict__ b2, float* __restrict__ out, int G)
{
    int gt = blockIdx.x * blockDim.x + threadIdx.x;
    int g = gt >> 5, lane = gt & 31;
    if (g >= G) return;
    const float* a = OUT + (size_t)g * HIDC;
    float s = 0.f;
    #pragma unroll
    for (int i = 0; i < 4; i++) s += a[lane + i * 32] * W2[lane + i * 32];
    #pragma unroll
    for (int off = 16; off; off >>= 1) s += __shfl_xor_sync(0xFFFFFFFFu, s, off);
    if (lane == 0) out[g] = s + b2[0];
}

// ---------------------------------------------------------------------------
// Host
// ---------------------------------------------------------------------------
static inline int cdiv(int a, int b) { return (a + b - 1) / b; }

extern "C" void kernel_launch(void* const* d_in, const int* in_sizes, int n_in,
                              void* d_out, int out_size)
{
    const float* x      = (const float*)d_in[0];
    const int*   ei     = (const int*)  d_in[1];
    const int*   batch  = (const int*)  d_in[2];
    const float* W1     = (const float*)d_in[3];
    const float* b1     = (const float*)d_in[4];
    const float* Wg1    = (const float*)d_in[5];
    const float* att_l  = (const float*)d_in[6];
    const float* att_r  = (const float*)d_in[7];
    const float* Wg2    = (const float*)d_in[8];
    const float* bg     = (const float*)d_in[9];
    const float* Wih0   = (const float*)d_in[10];
    const float* Whh0   = (const float*)d_in[11];
    const float* bih0   = (const float*)d_in[12];
    const float* bhh0   = (const float*)d_in[13];
    const float* Wa     = (const float*)d_in[14];
    const float* asrc_a = (const float*)d_in[15];
    const float* adst_a = (const float*)d_in[16];
    const float* ba     = (const float*)d_in[17];
    const float* Wih_a  = (const float*)d_in[18];
    const float* Whh_a  = (const float*)d_in[19];
    const float* bih_a  = (const float*)d_in[20];
    const float* bhh_a  = (const float*)d_in[21];
    const float* Wm     = (const float*)d_in[22];
    const float* asrc_m = (const float*)d_in[23];
    const float* adst_m = (const float*)d_in[24];
    const float* bm     = (const float*)d_in[25];
    const float* Wih_m  = (const float*)d_in[26];
    const float* Whh_m  = (const float*)d_in[27];
    const float* bih_m  = (const float*)d_in[28];
    const float* bhh_m  = (const float*)d_in[29];
    const float* W2     = (const float*)d_in[30];
    const float* b2     = (const float*)d_in[31];
    float* out = (float*)d_out;

    const int N = in_sizes[0] / 64;
    const int E = in_sizes[1] / 2;
    const int G = out_size;
    const int* src = ei;
    const int* dst = ei + E;

    float *X, *Z, *H, *GI, *GH, *al, *ar, *m, *sum, *cE, *Wg1p;
    float *OUT, *OT, *H2, *GI2, *GH2, *ad;
    cudaGetSymbolAddress((void**)&X,  g_X);
    cudaGetSymbolAddress((void**)&Z,  g_Z);
    cudaGetSymbolAddress((void**)&H,  g_H);
    cudaGetSymbolAddress((void**)&GI, g_GI);
    cudaGetSymbolAddress((void**)&GH, g_GH);
    cudaGetSymbolAddress((void**)&al, g_al);
    cudaGetSymbolAddress((void**)&ar, g_ar);
    cudaGetSymbolAddress((void**)&m,  g_m);
    cudaGetSymbolAddress((void**)&sum,g_sum);
    cudaGetSymbolAddress((void**)&cE, g_cE);
    cudaGetSymbolAddress((void**)&Wg1p, g_Wg1p);
    cudaGetSymbolAddress((void**)&OUT,g_OUT);
    cudaGetSymbolAddress((void**)&OT, g_OT);
    cudaGetSymbolAddress((void**)&H2, g_H2);
    cudaGetSymbolAddress((void**)&GI2,g_GI2);
    cudaGetSymbolAddress((void**)&GH2,g_GH2);
    cudaGetSymbolAddress((void**)&ad, g_ad);

    // Tensor-core GEMM launcher: C[N,M] = act(A*W^T + bias), M%128==0, K%32==0
    auto gemm = [&](const float* A, int lda, const float* W, int ldw,
                    const float* bias, float* C, int n, int mm, int k, int act) {
        dim3 grid(mm / 128, cdiv(n, 128));
        gemm_bf<<<grid, 256>>>(A, lda, W, ldw, bias, C, n, mm, k, act);
    };

    const int T256_N   = cdiv(N, 256);
    const int T256_NC  = cdiv(N * HIDC, 256);
    const int T256_E   = cdiv(E, 256);
    const int WARP_E   = cdiv(E * 32, 256);
    const int WARP_N   = cdiv(N * 32, 256);

    auto message_pass = [&](const float* bias_vec) {
        fill_u32<<<T256_N, 256>>>((unsigned int*)m, 0xFF800000u, N);
        fill_f32<<<T256_N, 256>>>(sum, 0.f, N);
        fill_f32<<<T256_NC, 256>>>(H, 0.f, N * HIDC);
        edge_max      <<<T256_E, 256>>>(src, dst, E, al, ar, m);
        edge_scatter_f<<<WARP_E, 256>>>(src, dst, E, al, ar, m, sum, Z, H);
        bias_elu_div  <<<T256_NC, 256>>>(H, sum, bias_vec, N * HIDC);
    };
    auto gru_big = [&](const float* Wih, const float* Whh,
                       const float* bih, const float* bhh) {
        gemm(H, HIDC, Wih, HIDC, bih, GI, N, H3C, HIDC, 0);
        gemm(X, HIDC, Whh, HIDC, bhh, GH, N, H3C, HIDC, 0);
        gru_gate<<<T256_NC, 256>>>(GI, GH, X, N);
    };

    // ---- Stage 0: x = leaky(x @ W1^T + b1) ----
    comp_cedge<<<1, 128>>>(Wg1, cE);
    pack_wg1<<<64, 256>>>(Wg1, Wg1p);
    gemm(x, 64, W1, 64, b1, X, N, HIDC, 64, 1);

    // ---- Stage 1: GATEConv + GRU ----
    gemm(X, HIDC, Wg1p, HIDC, cE, H, N, HIDC, HIDC, 1);
    rowdot<<<WARP_N, 256>>>(H, att_l, al, N);
    rowdot<<<WARP_N, 256>>>(X, att_r, ar, N);
    gemm(X, HIDC, Wg2, HIDC, nullptr, Z, N, HIDC, HIDC, 0);
    message_pass(bg);
    gru_big(Wih0, Whh0, bih0, bhh0);

    // ---- Stage 2: 2 x (GATConv + GRU) ----
    for (int l = 0; l < 2; l++) {
        gemm(X, HIDC, Wa + (size_t)l * HIDC * HIDC, HIDC, nullptr, Z, N, HIDC, HIDC, 0);
        rowdot<<<WARP_N, 256>>>(Z, asrc_a + l * HIDC, al, N);
        rowdot<<<WARP_N, 256>>>(Z, adst_a + l * HIDC, ar, N);
        message_pass(ba + l * HIDC);
        gru_big(Wih_a + (size_t)l * H3C * HIDC, Whh_a + (size_t)l * H3C * HIDC,
                bih_a + l * H3C, bhh_a + l * H3C);
    }

    // ---- Stage 3: attentive readout ----
    const int T256_G  = cdiv(G, 256);
    const int T256_GC = cdiv(G * HIDC, 256);
    const int WARP_G  = cdiv(G * 32, 256);

    fill_f32<<<T256_GC, 256>>>(OUT, 0.f, G * HIDC);
    node_scatter_sum<<<WARP_N, 256>>>(batch, X, OUT, N);
    relu_ip<<<T256_GC, 256>>>(OUT, G * HIDC);

    gemm(X, HIDC, Wm, HIDC, nullptr, Z, N, HIDC, HIDC, 0);
    rowdot<<<WARP_N, 256>>>(Z, asrc_m, al, N);

    for (int t = 0; t < 3; t++) {
        gemm(OUT, HIDC, Wm, HIDC, nullptr, OT, G, HIDC, HIDC, 0);
        rowdot<<<WARP_G, 256>>>(OT, adst_m, ad, G);
        fill_u32<<<T256_G, 256>>>((unsigned int*)m, 0xFF800000u, G);
        fill_f32<<<T256_G, 256>>>(sum, 0.f, G);
        fill_f32<<<T256_GC, 256>>>(H2, 0.f, G * HIDC);
        node_max      <<<T256_N, 256>>>(batch, N, al, ad, m);
        node_scatter_f<<<WARP_N, 256>>>(batch, N, al, ad, m, sum, Z, H2);
        bias_elu_div  <<<T256_GC, 256>>>(H2, sum, bm, G * HIDC);
        gemm(H2,  HIDC, Wih_m, HIDC, bih_m, GI2, G, H3C, HIDC, 0);
        gemm(OUT, HIDC, Whh_m, HIDC, bhh_m, GH2, G, H3C, HIDC, 0);
        gru_gate<<<T256_GC, 256>>>(GI2, GH2, OUT, G);
    }

    final_out<<<WARP_G, 256>>>(OUT, W2, b2, out, G);
}

// round 8
// speedup vs baseline: 2.3195x; 1.0225x over previous
#include <cuda_runtime.h>
#include <cuda_bf16.h>
#include <math.h>
#include <stdint.h>

// ---------------------------------------------------------------------------
// Problem constants
// ---------------------------------------------------------------------------
#define NMAX   50000
#define EMAX   800000
#define GMAX   1024
#define HIDC   128
#define H3C    384
#define NEGS   0.01f

// ---------------------------------------------------------------------------
// Scratch (device globals; no allocation allowed)
// ---------------------------------------------------------------------------
__device__ float g_X  [(size_t)NMAX * HIDC];
__device__ float g_Z  [(size_t)NMAX * HIDC];
__device__ float g_H  [(size_t)NMAX * HIDC];
__device__ float g_GI [(size_t)NMAX * H3C];
__device__ float g_GH [(size_t)NMAX * H3C];
__device__ float g_al [NMAX];
__device__ float g_ar [NMAX];
__device__ float g_m  [NMAX];
__device__ float g_sum[NMAX];
__device__ float g_cE [HIDC];
__device__ float g_Wg1p[HIDC * HIDC];
__device__ float g_OUT [GMAX * HIDC];
__device__ float g_OT  [GMAX * HIDC];
__device__ float g_H2  [GMAX * HIDC];
__device__ float g_GI2 [GMAX * H3C];
__device__ float g_GH2 [GMAX * H3C];
__device__ float g_ad  [GMAX];

// bf16 hi/lo planes (packed pairs, u32 = 2 bf16). kp = K/2 per row.
__device__ uint32_t g_XAh[(size_t)NMAX * 64], g_XAl[(size_t)NMAX * 64];
__device__ uint32_t g_HAh[(size_t)NMAX * 64], g_HAl[(size_t)NMAX * 64];
__device__ uint32_t g_OAh[GMAX * 64],  g_OAl[GMAX * 64];
__device__ uint32_t g_H2Ah[GMAX * 64], g_H2Al[GMAX * 64];
// weight planes
__device__ uint32_t g_wW1h[128 * 32],  g_wW1l[128 * 32];
__device__ uint32_t g_wWg1h[128 * 64], g_wWg1l[128 * 64];
__device__ uint32_t g_wWg2h[128 * 64], g_wWg2l[128 * 64];
__device__ uint32_t g_wWih0h[384 * 64], g_wWih0l[384 * 64];
__device__ uint32_t g_wWhh0h[384 * 64], g_wWhh0l[384 * 64];
__device__ uint32_t g_wWah[2 * 128 * 64], g_wWal[2 * 128 * 64];
__device__ uint32_t g_wWihah[2 * 384 * 64], g_wWihal[2 * 384 * 64];
__device__ uint32_t g_wWhhah[2 * 384 * 64], g_wWhhal[2 * 384 * 64];
__device__ uint32_t g_wWmh[128 * 64],  g_wWml[128 * 64];
__device__ uint32_t g_wWihmh[384 * 64], g_wWihml[384 * 64];
__device__ uint32_t g_wWhhmh[384 * 64], g_wWhhml[384 * 64];

// ---------------------------------------------------------------------------
// Helpers
// ---------------------------------------------------------------------------
__device__ __forceinline__ float leaky_f(float v) { return v >= 0.f ? v : NEGS * v; }

__device__ __forceinline__ void atomicMaxFloat(float* addr, float val) {
    if (val >= 0.f) atomicMax((int*)addr, __float_as_int(val));
    else            atomicMin((unsigned int*)addr, __float_as_uint(val));
}

__device__ __forceinline__ void redv4(float* p, float a, float b, float c, float d) {
    asm volatile("red.global.add.v4.f32 [%0], {%1,%2,%3,%4};"
                 :: "l"(p), "f"(a), "f"(b), "f"(c), "f"(d) : "memory");
}

__device__ __forceinline__ void split2(float a, float b, uint32_t& hi, uint32_t& lo) {
    __nv_bfloat16 ah = __float2bfloat16_rn(a);
    __nv_bfloat16 bh = __float2bfloat16_rn(b);
    __nv_bfloat162 h; h.x = ah; h.y = bh;
    hi = *reinterpret_cast<uint32_t*>(&h);
    __nv_bfloat162 l;
    l.x = __float2bfloat16_rn(a - __bfloat162float(ah));
    l.y = __float2bfloat16_rn(b - __bfloat162float(bh));
    lo = *reinterpret_cast<uint32_t*>(&l);
}

__device__ __forceinline__ void mma_bf16(float c[4], const uint32_t a[4], const uint32_t b[2]) {
    asm volatile("mma.sync.aligned.m16n8k16.row.col.f32.bf16.bf16.f32 "
        "{%0,%1,%2,%3}, {%4,%5,%6,%7}, {%8,%9}, {%0,%1,%2,%3};"
        : "+f"(c[0]), "+f"(c[1]), "+f"(c[2]), "+f"(c[3])
        : "r"(a[0]), "r"(a[1]), "r"(a[2]), "r"(a[3]), "r"(b[0]), "r"(b[1]));
}

__device__ __forceinline__ void cp16(uint32_t* s, const uint32_t* g) {
    uint32_t sa = (uint32_t)__cvta_generic_to_shared(s);
    asm volatile("cp.async.cg.shared.global [%0], [%1], 16;" :: "r"(sa), "l"(g));
}

// ---------------------------------------------------------------------------
// Split matrix into bf16 hi/lo packed planes: pairs = n*k/2
// ---------------------------------------------------------------------------
__global__ void split_mat(const float* __restrict__ A, uint32_t* __restrict__ hi,
                          uint32_t* __restrict__ lo, int pairs)
{
    int i = blockIdx.x * blockDim.x + threadIdx.x;
    if (i >= pairs) return;
    float2 v = reinterpret_cast<const float2*>(A)[i];
    uint32_t h, l;
    split2(v.x, v.y, h, l);
    hi[i] = h; lo[i] = l;
}

// ---------------------------------------------------------------------------
// Plane GEMM: C[N,M] = act(A[N,K] * W[M,K]^T + bias), planes pre-split.
// Full K resident in smem (K <= 128). BM=128, BN=128 (one col group per
// blockIdx.x). 256 threads = 8 warps (2x4), warp tile 64x32.
// ---------------------------------------------------------------------------
#define SP 68   // smem pair stride (64 + 4 pad; keeps 16B alignment, no conflicts)
#define GEMM_SMEM (4 * 128 * SP * 4)

__global__ __launch_bounds__(256)
void gemm_p(const uint32_t* __restrict__ Ah, const uint32_t* __restrict__ Al,
            const uint32_t* __restrict__ Wh, const uint32_t* __restrict__ Wl,
            const float* __restrict__ bias, float* __restrict__ C,
            int N, int M, int K, int act)
{
    extern __shared__ uint32_t smem[];
    uint32_t* sAh = smem;
    uint32_t* sAl = smem + 128 * SP;
    uint32_t* sWh = smem + 2 * 128 * SP;
    uint32_t* sWl = smem + 3 * 128 * SP;

    const int tid  = threadIdx.x;
    const int lane = tid & 31;
    const int warp = tid >> 5;
    const int gID  = lane >> 2;
    const int tig  = lane & 3;
    const int row0 = blockIdx.y * 128;
    const int col0 = blockIdx.x * 128;
    const int warpM = (warp >> 2) * 64;
    const int warpN = (warp & 3) * 32;

    const int kp  = K >> 1;          // u32 per row
    const int sh  = (kp == 64) ? 4 : 3;  // log2(kp/4)
    const int kp4 = kp >> 2;         // 16B segs per row
    const int msk = kp4 - 1;

    // async loads: A tile (guarded by N), W tile (M multiple of 128)
    for (int s = tid; s < 128 * kp4; s += 256) {
        int r = s >> sh, c = (s & msk) << 2;
        int gr = row0 + r;
        if (gr < N) {
            cp16(&sAh[r * SP + c], Ah + (size_t)gr * kp + c);
            cp16(&sAl[r * SP + c], Al + (size_t)gr * kp + c);
        }
        int gw = col0 + r;
        cp16(&sWh[r * SP + c], Wh + (size_t)gw * kp + c);
        cp16(&sWl[r * SP + c], Wl + (size_t)gw * kp + c);
    }
    asm volatile("cp.async.commit_group;");
    asm volatile("cp.async.wait_group 0;");
    __syncthreads();

    float c[4][4][4];
    #pragma unroll
    for (int i = 0; i < 4; i++)
        #pragma unroll
        for (int j = 0; j < 4; j++)
            #pragma unroll
            for (int q = 0; q < 4; q++) c[i][j][q] = 0.f;

    const int nks = K >> 4;
    for (int ks = 0; ks < nks; ks++) {
        const int pb = ks * 8;
        uint32_t ah[4][4], alr[4][4], bh[4][2], blr[4][2];
        #pragma unroll
        for (int i = 0; i < 4; i++) {
            int b0 = (warpM + i * 16 + gID) * SP + pb + tig;
            int b8 = b0 + 8 * SP;
            ah[i][0] = sAh[b0];     ah[i][1] = sAh[b8];
            ah[i][2] = sAh[b0 + 4]; ah[i][3] = sAh[b8 + 4];
            alr[i][0] = sAl[b0];     alr[i][1] = sAl[b8];
            alr[i][2] = sAl[b0 + 4]; alr[i][3] = sAl[b8 + 4];
        }
        #pragma unroll
        for (int j = 0; j < 4; j++) {
            int wb = (warpN + j * 8 + gID) * SP + pb + tig;
            bh[j][0] = sWh[wb]; bh[j][1] = sWh[wb + 4];
            blr[j][0] = sWl[wb]; blr[j][1] = sWl[wb + 4];
        }
        // three independent combo passes (no accumulator RAW chains)
        #pragma unroll
        for (int i = 0; i < 4; i++)
            #pragma unroll
            for (int j = 0; j < 4; j++) mma_bf16(c[i][j], ah[i], bh[j]);
        #pragma unroll
        for (int i = 0; i < 4; i++)
            #pragma unroll
            for (int j = 0; j < 4; j++) mma_bf16(c[i][j], alr[i], bh[j]);
        #pragma unroll
        for (int i = 0; i < 4; i++)
            #pragma unroll
            for (int j = 0; j < 4; j++) mma_bf16(c[i][j], ah[i], blr[j]);
    }

    // Epilogue
    #pragma unroll
    for (int i = 0; i < 4; i++) {
        int r_lo = row0 + warpM + i * 16 + gID;
        int r_hi = r_lo + 8;
        #pragma unroll
        for (int j = 0; j < 4; j++) {
            int cc = col0 + warpN + j * 8 + tig * 2;
            float b0 = bias ? bias[cc] : 0.f;
            float b1 = bias ? bias[cc + 1] : 0.f;
            float v0 = c[i][j][0] + b0, v1 = c[i][j][1] + b1;
            float v2 = c[i][j][2] + b0, v3 = c[i][j][3] + b1;
            if (act == 1) { v0 = leaky_f(v0); v1 = leaky_f(v1); v2 = leaky_f(v2); v3 = leaky_f(v3); }
            if (r_lo < N) {
                C[(size_t)r_lo * M + cc]     = v0;
                C[(size_t)r_lo * M + cc + 1] = v1;
            }
            if (r_hi < N) {
                C[(size_t)r_hi * M + cc]     = v2;
                C[(size_t)r_hi * M + cc + 1] = v3;
            }
        }
    }
}

// ---------------------------------------------------------------------------
// Small elementwise / utility kernels
// ---------------------------------------------------------------------------
__global__ void fill_f32(float* p, float v, int n) {
    int i = blockIdx.x * blockDim.x + threadIdx.x;
    if (i < n) p[i] = v;
}
__global__ void fill_u32(unsigned int* p, unsigned int v, int n) {
    int i = blockIdx.x * blockDim.x + threadIdx.x;
    if (i < n) p[i] = v;
}

__global__ void comp_cedge(const float* __restrict__ Wg1, float* __restrict__ cE) {
    int m = threadIdx.x;
    if (m < HIDC) {
        float s = 0.f;
        #pragma unroll
        for (int j = 0; j < 25; j++) s += Wg1[(size_t)m * 153 + 128 + j];
        cE[m] = s;
    }
}

__global__ void pack_wg1(const float* __restrict__ Wg1, float* __restrict__ out) {
    int i = blockIdx.x * blockDim.x + threadIdx.x;
    if (i < HIDC * HIDC) {
        int r = i >> 7, c = i & 127;
        out[i] = Wg1[(size_t)r * 153 + c];
    }
}

__global__ void rowdot(const float* __restrict__ A, const float* __restrict__ v,
                       float* __restrict__ out, int N)
{
    int gt = blockIdx.x * blockDim.x + threadIdx.x;
    int row = gt >> 5, lane = gt & 31;
    if (row >= N) return;
    const float* a = A + (size_t)row * HIDC;
    float s = 0.f;
    #pragma unroll
    for (int i = 0; i < 4; i++) s += a[lane + i * 32] * v[lane + i * 32];
    #pragma unroll
    for (int off = 16; off; off >>= 1) s += __shfl_xor_sync(0xFFFFFFFFu, s, off);
    if (lane == 0) out[row] = s;
}

// ---------------------------------------------------------------------------
// Edge-segment softmax + scatter
// ---------------------------------------------------------------------------
__global__ void edge_max(const int* __restrict__ src, const int* __restrict__ dst, int E,
                         const float* __restrict__ al, const float* __restrict__ ar,
                         float* __restrict__ m)
{
    int e = blockIdx.x * blockDim.x + threadIdx.x;
    if (e >= E) return;
    float v = leaky_f(al[src[e]] + ar[dst[e]]);
    atomicMaxFloat(&m[dst[e]], v);
}

__global__ void edge_scatter_f(const int* __restrict__ src, const int* __restrict__ dst, int E,
                               const float* __restrict__ al, const float* __restrict__ ar,
                               const float* __restrict__ m, float* __restrict__ ssum,
                               const float* __restrict__ Z, float* __restrict__ H)
{
    int gt = blockIdx.x * blockDim.x + threadIdx.x;
    int e = gt >> 5, lane = gt & 31;
    if (e >= E) return;
    int s = src[e], d = dst[e];
    float v = leaky_f(al[s] + ar[d]);
    float w = expf(v - m[d]);
    if (lane == 0) atomicAdd(&ssum[d], w);
    float4 z = reinterpret_cast<const float4*>(Z + (size_t)s * HIDC)[lane];
    redv4(H + (size_t)d * HIDC + lane * 4, z.x * w, z.y * w, z.z * w, z.w * w);
}

__global__ void bias_elu_div(float* __restrict__ H, const float* __restrict__ ssum,
                             const float* __restrict__ b, int total) {
    int i = blockIdx.x * blockDim.x + threadIdx.x;
    if (i >= total) return;
    int n = i >> 7, c = i & (HIDC - 1);
    float v = H[i] / (ssum[n] + 1e-16f) + b[c];
    H[i] = v > 0.f ? v : expm1f(v);
}

__global__ void gru_gate(const float* __restrict__ GI, const float* __restrict__ GH,
                         float* __restrict__ X, int N)
{
    int i = blockIdx.x * blockDim.x + threadIdx.x;
    if (i >= N * HIDC) return;
    int n = i >> 7, c = i & (HIDC - 1);
    const float* gi = GI + (size_t)n * H3C;
    const float* gh = GH + (size_t)n * H3C;
    float r  = 1.f / (1.f + expf(-(gi[c]       + gh[c])));
    float z  = 1.f / (1.f + expf(-(gi[c + 128] + gh[c + 128])));
    float nn = tanhf(gi[c + 256] + r * gh[c + 256]);
    float o  = (1.f - z) * nn + z * X[i];
    X[i] = fmaxf(o, 0.f);
}

// ---------------------------------------------------------------------------
// Readout kernels
// ---------------------------------------------------------------------------
__global__ void node_scatter_sum(const int* __restrict__ batch, const float* __restrict__ X,
                                 float* __restrict__ OUT, int N)
{
    int gt = blockIdx.x * blockDim.x + threadIdx.x;
    int n = gt >> 5, lane = gt & 31;
    if (n >= N) return;
    int b = batch[n];
    float4 v = reinterpret_cast<const float4*>(X + (size_t)n * HIDC)[lane];
    redv4(OUT + (size_t)b * HIDC + lane * 4, v.x, v.y, v.z, v.w);
}

__global__ void relu_ip(float* p, int n) {
    int i = blockIdx.x * blockDim.x + threadIdx.x;
    if (i < n) p[i] = fmaxf(p[i], 0.f);
}

__global__ void node_max(const int* __restrict__ batch, int N,
                         const float* __restrict__ asrc, const float* __restrict__ adst,
                         float* __restrict__ m)
{
    int n = blockIdx.x * blockDim.x + threadIdx.x;
    if (n >= N) return;
    int b = batch[n];
    atomicMaxFloat(&m[b], leaky_f(asrc[n] + adst[b]));
}

__global__ void node_scatter_f(const int* __restrict__ batch, int N,
                               const float* __restrict__ asrc, const float* __restrict__ adst,
                               const float* __restrict__ m, float* __restrict__ ssum,
                               const float* __restrict__ XT, float* __restrict__ H2)
{
    int gt = blockIdx.x * blockDim.x + threadIdx.x;
    int n = gt >> 5, lane = gt & 31;
    if (n >= N) return;
    int b = batch[n];
    float w = expf(leaky_f(asrc[n] + adst[b]) - m[b]);
    if (lane == 0) atomicAdd(&ssum[b], w);
    float4 v = reinterpret_cast<const float4*>(XT + (size_t)n * HIDC)[lane];
    redv4(H2 + (size_t)b * HIDC + lane * 4, v.x * w, v.y * w, v.z * w, v.w * w);
}

__global__ void final_out(const float* __restrict__ OUT, const float* __restrict__ W2,
                          const float* __restrict__ b2, float* __restrict__ out, int G)
{
    int gt = blockIdx.x * blockDim.x + threadIdx.x;
    int g = gt >> 5, lane = gt & 31;
    if (g >= G) return;
    const float* a = OUT + (size_t)g * HIDC;
    float s = 0.f;
    #pragma unroll
    for (int i = 0; i < 4; i++) s += a[lane + i * 32] * W2[lane + i * 32];
    #pragma unroll
    for (int off = 16; off; off >>= 1) s += __shfl_xor_sync(0xFFFFFFFFu, s, off);
    if (lane == 0) out[g] = s + b2[0];
}

// ---------------------------------------------------------------------------
// Host
// ---------------------------------------------------------------------------
static inline int cdiv(int a, int b) { return (a + b - 1) / b; }

#define SYM(var, sym) cudaGetSymbolAddress((void**)&var, sym)

extern "C" void kernel_launch(void* const* d_in, const int* in_sizes, int n_in,
                              void* d_out, int out_size)
{
    const float* x      = (const float*)d_in[0];
    const int*   ei     = (const int*)  d_in[1];
    const int*   batch  = (const int*)  d_in[2];
    const float* W1     = (const float*)d_in[3];
    const float* b1     = (const float*)d_in[4];
    const float* Wg1    = (const float*)d_in[5];
    const float* att_l  = (const float*)d_in[6];
    const float* att_r  = (const float*)d_in[7];
    const float* Wg2    = (const float*)d_in[8];
    const float* bg     = (const float*)d_in[9];
    const float* Wih0   = (const float*)d_in[10];
    const float* Whh0   = (const float*)d_in[11];
    const float* bih0   = (const float*)d_in[12];
    const float* bhh0   = (const float*)d_in[13];
    const float* Wa     = (const float*)d_in[14];
    const float* asrc_a = (const float*)d_in[15];
    const float* adst_a = (const float*)d_in[16];
    const float* ba     = (const float*)d_in[17];
    const float* Wih_a  = (const float*)d_in[18];
    const float* Whh_a  = (const float*)d_in[19];
    const float* bih_a  = (const float*)d_in[20];
    const float* bhh_a  = (const float*)d_in[21];
    const float* Wm     = (const float*)d_in[22];
    const float* asrc_m = (const float*)d_in[23];
    const float* adst_m = (const float*)d_in[24];
    const float* bm     = (const float*)d_in[25];
    const float* Wih_m  = (const float*)d_in[26];
    const float* Whh_m  = (const float*)d_in[27];
    const float* bih_m  = (const float*)d_in[28];
    const float* bhh_m  = (const float*)d_in[29];
    const float* W2     = (const float*)d_in[30];
    const float* b2     = (const float*)d_in[31];
    float* out = (float*)d_out;

    const int N = in_sizes[0] / 64;
    const int E = in_sizes[1] / 2;
    const int G = out_size;
    const int* src = ei;
    const int* dst = ei + E;

    static int smem_set = 0;
    if (!smem_set) {
        cudaFuncSetAttribute(gemm_p, cudaFuncAttributeMaxDynamicSharedMemorySize, GEMM_SMEM);
        smem_set = 1;
    }

    float *X, *Z, *H, *GI, *GH, *al, *ar, *m, *sum, *cE, *Wg1p;
    float *OUT, *OT, *H2, *GI2, *GH2, *ad;
    SYM(X, g_X); SYM(Z, g_Z); SYM(H, g_H); SYM(GI, g_GI); SYM(GH, g_GH);
    SYM(al, g_al); SYM(ar, g_ar); SYM(m, g_m); SYM(sum, g_sum);
    SYM(cE, g_cE); SYM(Wg1p, g_Wg1p);
    SYM(OUT, g_OUT); SYM(OT, g_OT); SYM(H2, g_H2);
    SYM(GI2, g_GI2); SYM(GH2, g_GH2); SYM(ad, g_ad);

    uint32_t *XAh, *XAl, *HAh, *HAl, *OAh, *OAl, *H2Ah, *H2Al;
    SYM(XAh, g_XAh); SYM(XAl, g_XAl); SYM(HAh, g_HAh); SYM(HAl, g_HAl);
    SYM(OAh, g_OAh); SYM(OAl, g_OAl); SYM(H2Ah, g_H2Ah); SYM(H2Al, g_H2Al);

    uint32_t *wW1h,*wW1l,*wWg1h,*wWg1l,*wWg2h,*wWg2l,*wWih0h,*wWih0l,*wWhh0h,*wWhh0l;
    uint32_t *wWah,*wWal,*wWihah,*wWihal,*wWhhah,*wWhhal,*wWmh,*wWml,*wWihmh,*wWihml,*wWhhmh,*wWhhml;
    SYM(wW1h, g_wW1h); SYM(wW1l, g_wW1l);
    SYM(wWg1h, g_wWg1h); SYM(wWg1l, g_wWg1l);
    SYM(wWg2h, g_wWg2h); SYM(wWg2l, g_wWg2l);
    SYM(wWih0h, g_wWih0h); SYM(wWih0l, g_wWih0l);
    SYM(wWhh0h, g_wWhh0h); SYM(wWhh0l, g_wWhh0l);
    SYM(wWah, g_wWah); SYM(wWal, g_wWal);
    SYM(wWihah, g_wWihah); SYM(wWihal, g_wWihal);
    SYM(wWhhah, g_wWhhah); SYM(wWhhal, g_wWhhal);
    SYM(wWmh, g_wWmh); SYM(wWml, g_wWml);
    SYM(wWihmh, g_wWihmh); SYM(wWihml, g_wWihml);
    SYM(wWhhmh, g_wWhhmh); SYM(wWhhml, g_wWhhml);

    auto split = [&](const float* A, uint32_t* hi, uint32_t* lo, int pairs) {
        split_mat<<<cdiv(pairs, 256), 256>>>(A, hi, lo, pairs);
    };
    auto gemm = [&](const uint32_t* Ah, const uint32_t* Al,
                    const uint32_t* Wh, const uint32_t* Wl,
                    const float* bias, float* C, int n, int mm, int k, int act) {
        dim3 grid(mm / 128, cdiv(n, 128));
        gemm_p<<<grid, 256, GEMM_SMEM>>>(Ah, Al, Wh, Wl, bias, C, n, mm, k, act);
    };

    const int T256_N   = cdiv(N, 256);
    const int T256_NC  = cdiv(N * HIDC, 256);
    const int T256_E   = cdiv(E, 256);
    const int WARP_E   = cdiv(E * 32, 256);
    const int WARP_N   = cdiv(N * 32, 256);

    auto message_pass = [&](const float* bias_vec) {
        fill_u32<<<T256_N, 256>>>((unsigned int*)m, 0xFF800000u, N);
        fill_f32<<<T256_N, 256>>>(sum, 0.f, N);
        fill_f32<<<T256_NC, 256>>>(H, 0.f, N * HIDC);
        edge_max      <<<T256_E, 256>>>(src, dst, E, al, ar, m);
        edge_scatter_f<<<WARP_E, 256>>>(src, dst, E, al, ar, m, sum, Z, H);
        bias_elu_div  <<<T256_NC, 256>>>(H, sum, bias_vec, N * HIDC);
    };

    // ---- weight prep (every call; deterministic) ----
    comp_cedge<<<1, 128>>>(Wg1, cE);
    pack_wg1<<<64, 256>>>(Wg1, Wg1p);
    split(W1,   wW1h,   wW1l,   128 * 32);
    split(Wg1p, wWg1h,  wWg1l,  128 * 64);
    split(Wg2,  wWg2h,  wWg2l,  128 * 64);
    split(Wih0, wWih0h, wWih0l, 384 * 64);
    split(Whh0, wWhh0h, wWhh0l, 384 * 64);
    split(Wa,   wWah,   wWal,   2 * 128 * 64);
    split(Wih_a, wWihah, wWihal, 2 * 384 * 64);
    split(Whh_a, wWhhah, wWhhal, 2 * 384 * 64);
    split(Wm,   wWmh,   wWml,   128 * 64);
    split(Wih_m, wWihmh, wWihml, 384 * 64);
    split(Whh_m, wWhhmh, wWhhml, 384 * 64);

    // ---- Stage 0: X = leaky(x @ W1^T + b1) ----
    split(x, XAh, XAl, N * 32);
    gemm(XAh, XAl, wW1h, wW1l, b1, X, N, 128, 64, 1);

    // ---- Stage 1: GATEConv + GRU ----
    split(X, XAh, XAl, N * 64);
    gemm(XAh, XAl, wWg1h, wWg1l, cE, H, N, 128, 128, 1);
    rowdot<<<WARP_N, 256>>>(H, att_l, al, N);
    rowdot<<<WARP_N, 256>>>(X, att_r, ar, N);
    gemm(XAh, XAl, wWg2h, wWg2l, nullptr, Z, N, 128, 128, 0);
    message_pass(bg);
    split(H, HAh, HAl, N * 64);
    gemm(HAh, HAl, wWih0h, wWih0l, bih0, GI, N, 384, 128, 0);
    gemm(XAh, XAl, wWhh0h, wWhh0l, bhh0, GH, N, 384, 128, 0);
    gru_gate<<<T256_NC, 256>>>(GI, GH, X, N);

    // ---- Stage 2: 2 x (GATConv + GRU) ----
    for (int l = 0; l < 2; l++) {
        split(X, XAh, XAl, N * 64);
        gemm(XAh, XAl, wWah + (size_t)l * 128 * 64, wWal + (size_t)l * 128 * 64,
             nullptr, Z, N, 128, 128, 0);
        rowdot<<<WARP_N, 256>>>(Z, asrc_a + l * HIDC, al, N);
        rowdot<<<WARP_N, 256>>>(Z, adst_a + l * HIDC, ar, N);
        message_pass(ba + l * HIDC);
        split(H, HAh, HAl, N * 64);
        gemm(HAh, HAl, wWihah + (size_t)l * 384 * 64, wWihal + (size_t)l * 384 * 64,
             bih_a + l * H3C, GI, N, 384, 128, 0);
        gemm(XAh, XAl, wWhhah + (size_t)l * 384 * 64, wWhhal + (size_t)l * 384 * 64,
             bhh_a + l * H3C, GH, N, 384, 128, 0);
        gru_gate<<<T256_NC, 256>>>(GI, GH, X, N);
    }

    // ---- Stage 3: attentive readout ----
    const int T256_G  = cdiv(G, 256);
    const int T256_GC = cdiv(G * HIDC, 256);
    const int WARP_G  = cdiv(G * 32, 256);

    fill_f32<<<T256_GC, 256>>>(OUT, 0.f, G * HIDC);
    node_scatter_sum<<<WARP_N, 256>>>(batch, X, OUT, N);
    relu_ip<<<T256_GC, 256>>>(OUT, G * HIDC);

    split(X, XAh, XAl, N * 64);
    gemm(XAh, XAl, wWmh, wWml, nullptr, Z, N, 128, 128, 0);
    rowdot<<<WARP_N, 256>>>(Z, asrc_m, al, N);

    for (int t = 0; t < 3; t++) {
        split(OUT, OAh, OAl, G * 64);
        gemm(OAh, OAl, wWmh, wWml, nullptr, OT, G, 128, 128, 0);
        rowdot<<<WARP_G, 256>>>(OT, adst_m, ad, G);
        fill_u32<<<T256_G, 256>>>((unsigned int*)m, 0xFF800000u, G);
        fill_f32<<<T256_G, 256>>>(sum, 0.f, G);
        fill_f32<<<T256_GC, 256>>>(H2, 0.f, G * HIDC);
        node_max      <<<T256_N, 256>>>(batch, N, al, ad, m);
        node_scatter_f<<<WARP_N, 256>>>(batch, N, al, ad, m, sum, Z, H2);
        bias_elu_div  <<<T256_GC, 256>>>(H2, sum, bm, G * HIDC);
        split(H2, H2Ah, H2Al, G * 64);
        gemm(H2Ah, H2Al, wWihmh, wWihml, bih_m, GI2, G, 384, 128, 0);
        gemm(OAh, OAl, wWhhmh, wWhhml, bhh_m, GH2, G, 384, 128, 0);
        gru_gate<<<T256_GC, 256>>>(GI2, GH2, OUT, G);
    }

    final_out<<<WARP_G, 256>>>(OUT, W2, b2, out, G);
}

// round 9
// speedup vs baseline: 2.5600x; 1.1037x over previous
#include <cuda_runtime.h>
#include <cuda_bf16.h>
#include <math.h>
#include <stdint.h>

// ---------------------------------------------------------------------------
// Problem constants
// ---------------------------------------------------------------------------
#define NMAX   50000
#define EMAX   800000
#define GMAX   1024
#define HIDC   128
#define H3C    384
#define NEGS   0.01f

// ---------------------------------------------------------------------------
// Scratch (device globals; no allocation allowed)
// ---------------------------------------------------------------------------
__device__ float g_X  [(size_t)NMAX * HIDC];
__device__ float g_Z  [(size_t)NMAX * HIDC];
__device__ float g_H  [(size_t)NMAX * HIDC];
__device__ float g_GI [(size_t)NMAX * H3C];
__device__ float g_GH [(size_t)NMAX * H3C];
__device__ float g_al [NMAX];
__device__ float g_ar [NMAX];
__device__ float g_sum[NMAX];
__device__ float g_cE [HIDC];
__device__ float g_Wg1p[HIDC * HIDC];
__device__ float g_OUT [GMAX * HIDC];
__device__ float g_OT  [GMAX * HIDC];
__device__ float g_H2  [GMAX * HIDC];
__device__ float g_GI2 [GMAX * H3C];
__device__ float g_GH2 [GMAX * H3C];
__device__ float g_ad  [GMAX];

// bf16 hi/lo planes (packed pairs, u32 = 2 bf16)
__device__ uint32_t g_xih[(size_t)NMAX * 32], g_xil[(size_t)NMAX * 32];  // input x (K=64)
__device__ uint32_t g_XAh[(size_t)NMAX * 64], g_XAl[(size_t)NMAX * 64];
__device__ uint32_t g_HAh[(size_t)NMAX * 64], g_HAl[(size_t)NMAX * 64];
__device__ uint32_t g_OAh[GMAX * 64],  g_OAl[GMAX * 64];
__device__ uint32_t g_H2Ah[GMAX * 64], g_H2Al[GMAX * 64];
// weight planes
__device__ uint32_t g_wW1h[128 * 32],  g_wW1l[128 * 32];
__device__ uint32_t g_wWg1h[128 * 64], g_wWg1l[128 * 64];
__device__ uint32_t g_wWg2h[128 * 64], g_wWg2l[128 * 64];
__device__ uint32_t g_wWih0h[384 * 64], g_wWih0l[384 * 64];
__device__ uint32_t g_wWhh0h[384 * 64], g_wWhh0l[384 * 64];
__device__ uint32_t g_wWah[2 * 128 * 64], g_wWal[2 * 128 * 64];
__device__ uint32_t g_wWihah[2 * 384 * 64], g_wWihal[2 * 384 * 64];
__device__ uint32_t g_wWhhah[2 * 384 * 64], g_wWhhal[2 * 384 * 64];
__device__ uint32_t g_wWmh[128 * 64],  g_wWml[128 * 64];
__device__ uint32_t g_wWihmh[384 * 64], g_wWihml[384 * 64];
__device__ uint32_t g_wWhhmh[384 * 64], g_wWhhml[384 * 64];

// ---------------------------------------------------------------------------
// Helpers
// ---------------------------------------------------------------------------
__device__ __forceinline__ float leaky_f(float v) { return v >= 0.f ? v : NEGS * v; }

__device__ __forceinline__ void redv4(float* p, float a, float b, float c, float d) {
    asm volatile("red.global.add.v4.f32 [%0], {%1,%2,%3,%4};"
                 :: "l"(p), "f"(a), "f"(b), "f"(c), "f"(d) : "memory");
}

__device__ __forceinline__ void split2(float a, float b, uint32_t& hi, uint32_t& lo) {
    __nv_bfloat16 ah = __float2bfloat16_rn(a);
    __nv_bfloat16 bh = __float2bfloat16_rn(b);
    __nv_bfloat162 h; h.x = ah; h.y = bh;
    hi = *reinterpret_cast<uint32_t*>(&h);
    __nv_bfloat162 l;
    l.x = __float2bfloat16_rn(a - __bfloat162float(ah));
    l.y = __float2bfloat16_rn(b - __bfloat162float(bh));
    lo = *reinterpret_cast<uint32_t*>(&l);
}

__device__ __forceinline__ void mma_bf16(float c[4], const uint32_t a[4], const uint32_t b[2]) {
    asm volatile("mma.sync.aligned.m16n8k16.row.col.f32.bf16.bf16.f32 "
        "{%0,%1,%2,%3}, {%4,%5,%6,%7}, {%8,%9}, {%0,%1,%2,%3};"
        : "+f"(c[0]), "+f"(c[1]), "+f"(c[2]), "+f"(c[3])
        : "r"(a[0]), "r"(a[1]), "r"(a[2]), "r"(a[3]), "r"(b[0]), "r"(b[1]));
}

__device__ __forceinline__ void cp16(uint32_t* s, const uint32_t* g) {
    uint32_t sa = (uint32_t)__cvta_generic_to_shared(s);
    asm volatile("cp.async.cg.shared.global [%0], [%1], 16;" :: "r"(sa), "l"(g));
}

// ---------------------------------------------------------------------------
// Split matrix into bf16 hi/lo packed planes (weights + input x only)
// ---------------------------------------------------------------------------
__global__ void split_mat(const float* __restrict__ A, uint32_t* __restrict__ hi,
                          uint32_t* __restrict__ lo, int pairs)
{
    int i = blockIdx.x * blockDim.x + threadIdx.x;
    if (i >= pairs) return;
    float2 v = reinterpret_cast<const float2*>(A)[i];
    uint32_t h, l;
    split2(v.x, v.y, h, l);
    hi[i] = h; lo[i] = l;
}

// ---------------------------------------------------------------------------
// Plane GEMM: C[N,M] = act(A[N,K] * W[M,K]^T + bias); optional plane output
// (Chi/Clo, only valid when M == 128). Full K resident, BM=BN=128, 8 warps.
// ---------------------------------------------------------------------------
#define SP 68
#define GEMM_SMEM (4 * 128 * SP * 4)

__global__ __launch_bounds__(256)
void gemm_p(const uint32_t* __restrict__ Ah, const uint32_t* __restrict__ Al,
            const uint32_t* __restrict__ Wh, const uint32_t* __restrict__ Wl,
            const float* __restrict__ bias, float* __restrict__ C,
            uint32_t* __restrict__ Chi, uint32_t* __restrict__ Clo,
            int N, int M, int K, int act)
{
    extern __shared__ uint32_t smem[];
    uint32_t* sAh = smem;
    uint32_t* sAl = smem + 128 * SP;
    uint32_t* sWh = smem + 2 * 128 * SP;
    uint32_t* sWl = smem + 3 * 128 * SP;

    const int tid  = threadIdx.x;
    const int lane = tid & 31;
    const int warp = tid >> 5;
    const int gID  = lane >> 2;
    const int tig  = lane & 3;
    const int row0 = blockIdx.y * 128;
    const int col0 = blockIdx.x * 128;
    const int warpM = (warp >> 2) * 64;
    const int warpN = (warp & 3) * 32;

    const int kp  = K >> 1;
    const int sh  = (kp == 64) ? 4 : 3;
    const int kp4 = kp >> 2;
    const int msk = kp4 - 1;

    for (int s = tid; s < 128 * kp4; s += 256) {
        int r = s >> sh, c = (s & msk) << 2;
        int gr = row0 + r;
        if (gr < N) {
            cp16(&sAh[r * SP + c], Ah + (size_t)gr * kp + c);
            cp16(&sAl[r * SP + c], Al + (size_t)gr * kp + c);
        }
        int gw = col0 + r;
        cp16(&sWh[r * SP + c], Wh + (size_t)gw * kp + c);
        cp16(&sWl[r * SP + c], Wl + (size_t)gw * kp + c);
    }
    asm volatile("cp.async.commit_group;");
    asm volatile("cp.async.wait_group 0;");
    __syncthreads();

    float c[4][4][4];
    #pragma unroll
    for (int i = 0; i < 4; i++)
        #pragma unroll
        for (int j = 0; j < 4; j++)
            #pragma unroll
            for (int q = 0; q < 4; q++) c[i][j][q] = 0.f;

    const int nks = K >> 4;
    for (int ks = 0; ks < nks; ks++) {
        const int pb = ks * 8;
        uint32_t ah[4][4], alr[4][4], bh[4][2], blr[4][2];
        #pragma unroll
        for (int i = 0; i < 4; i++) {
            int b0 = (warpM + i * 16 + gID) * SP + pb + tig;
            int b8 = b0 + 8 * SP;
            ah[i][0] = sAh[b0];     ah[i][1] = sAh[b8];
            ah[i][2] = sAh[b0 + 4]; ah[i][3] = sAh[b8 + 4];
            alr[i][0] = sAl[b0];     alr[i][1] = sAl[b8];
            alr[i][2] = sAl[b0 + 4]; alr[i][3] = sAl[b8 + 4];
        }
        #pragma unroll
        for (int j = 0; j < 4; j++) {
            int wb = (warpN + j * 8 + gID) * SP + pb + tig;
            bh[j][0] = sWh[wb]; bh[j][1] = sWh[wb + 4];
            blr[j][0] = sWl[wb]; blr[j][1] = sWl[wb + 4];
        }
        #pragma unroll
        for (int i = 0; i < 4; i++)
            #pragma unroll
            for (int j = 0; j < 4; j++) mma_bf16(c[i][j], ah[i], bh[j]);
        #pragma unroll
        for (int i = 0; i < 4; i++)
            #pragma unroll
            for (int j = 0; j < 4; j++) mma_bf16(c[i][j], alr[i], bh[j]);
        #pragma unroll
        for (int i = 0; i < 4; i++)
            #pragma unroll
            for (int j = 0; j < 4; j++) mma_bf16(c[i][j], ah[i], blr[j]);
    }

    const int mp = M >> 1;
    #pragma unroll
    for (int i = 0; i < 4; i++) {
        int r_lo = row0 + warpM + i * 16 + gID;
        int r_hi = r_lo + 8;
        #pragma unroll
        for (int j = 0; j < 4; j++) {
            int cc = col0 + warpN + j * 8 + tig * 2;
            float b0 = bias ? bias[cc] : 0.f;
            float b1 = bias ? bias[cc + 1] : 0.f;
            float v0 = c[i][j][0] + b0, v1 = c[i][j][1] + b1;
            float v2 = c[i][j][2] + b0, v3 = c[i][j][3] + b1;
            if (act == 1) { v0 = leaky_f(v0); v1 = leaky_f(v1); v2 = leaky_f(v2); v3 = leaky_f(v3); }
            if (r_lo < N) {
                C[(size_t)r_lo * M + cc]     = v0;
                C[(size_t)r_lo * M + cc + 1] = v1;
                if (Chi) {
                    uint32_t h, l; split2(v0, v1, h, l);
                    Chi[(size_t)r_lo * mp + (cc >> 1)] = h;
                    Clo[(size_t)r_lo * mp + (cc >> 1)] = l;
                }
            }
            if (r_hi < N) {
                C[(size_t)r_hi * M + cc]     = v2;
                C[(size_t)r_hi * M + cc + 1] = v3;
                if (Chi) {
                    uint32_t h, l; split2(v2, v3, h, l);
                    Chi[(size_t)r_hi * mp + (cc >> 1)] = h;
                    Clo[(size_t)r_hi * mp + (cc >> 1)] = l;
                }
            }
        }
    }
}

// ---------------------------------------------------------------------------
// Small elementwise / utility kernels
// ---------------------------------------------------------------------------
__global__ void fill_f32(float* p, float v, int n) {
    int i = blockIdx.x * blockDim.x + threadIdx.x;
    if (i < n) p[i] = v;
}

// zero sum[n] and H[n*128] in one launch
__global__ void fill_sum_H(float* __restrict__ ssum, float* __restrict__ H, int n) {
    int i = blockIdx.x * blockDim.x + threadIdx.x;
    if (i < n) ssum[i] = 0.f;
    if (i < n * HIDC) H[i] = 0.f;
}

__global__ void comp_cedge(const float* __restrict__ Wg1, float* __restrict__ cE) {
    int m = threadIdx.x;
    if (m < HIDC) {
        float s = 0.f;
        #pragma unroll
        for (int j = 0; j < 25; j++) s += Wg1[(size_t)m * 153 + 128 + j];
        cE[m] = s;
    }
}

__global__ void pack_wg1(const float* __restrict__ Wg1, float* __restrict__ out) {
    int i = blockIdx.x * blockDim.x + threadIdx.x;
    if (i < HIDC * HIDC) {
        int r = i >> 7, c = i & 127;
        out[i] = Wg1[(size_t)r * 153 + c];
    }
}

// out[row] = dot(A[row,:], v)
__global__ void rowdot(const float* __restrict__ A, const float* __restrict__ v,
                       float* __restrict__ out, int N)
{
    int gt = blockIdx.x * blockDim.x + threadIdx.x;
    int row = gt >> 5, lane = gt & 31;
    if (row >= N) return;
    const float* a = A + (size_t)row * HIDC;
    float s = 0.f;
    #pragma unroll
    for (int i = 0; i < 4; i++) s += a[lane + i * 32] * v[lane + i * 32];
    #pragma unroll
    for (int off = 16; off; off >>= 1) s += __shfl_xor_sync(0xFFFFFFFFu, s, off);
    if (lane == 0) out[row] = s;
}

// two dots over the SAME matrix in one pass: al = Z.va, ar = Z.vb
__global__ void rowdot2(const float* __restrict__ Z, const float* __restrict__ va,
                        const float* __restrict__ vb, float* __restrict__ al,
                        float* __restrict__ ar, int N)
{
    int gt = blockIdx.x * blockDim.x + threadIdx.x;
    int row = gt >> 5, lane = gt & 31;
    if (row >= N) return;
    const float* a = Z + (size_t)row * HIDC;
    float s = 0.f, t = 0.f;
    #pragma unroll
    for (int i = 0; i < 4; i++) {
        float z = a[lane + i * 32];
        s += z * va[lane + i * 32];
        t += z * vb[lane + i * 32];
    }
    #pragma unroll
    for (int off = 16; off; off >>= 1) {
        s += __shfl_xor_sync(0xFFFFFFFFu, s, off);
        t += __shfl_xor_sync(0xFFFFFFFFu, t, off);
    }
    if (lane == 0) { al[row] = s; ar[row] = t; }
}

// two dots over two different matrices (same row): al = A.va, ar = B.vb
__global__ void rowdot_ab(const float* __restrict__ A, const float* __restrict__ va,
                          const float* __restrict__ B, const float* __restrict__ vb,
                          float* __restrict__ al, float* __restrict__ ar, int N)
{
    int gt = blockIdx.x * blockDim.x + threadIdx.x;
    int row = gt >> 5, lane = gt & 31;
    if (row >= N) return;
    const float* a = A + (size_t)row * HIDC;
    const float* b = B + (size_t)row * HIDC;
    float s = 0.f, t = 0.f;
    #pragma unroll
    for (int i = 0; i < 4; i++) {
        s += a[lane + i * 32] * va[lane + i * 32];
        t += b[lane + i * 32] * vb[lane + i * 32];
    }
    #pragma unroll
    for (int off = 16; off; off >>= 1) {
        s += __shfl_xor_sync(0xFFFFFFFFu, s, off);
        t += __shfl_xor_sync(0xFFFFFFFFu, t, off);
    }
    if (lane == 0) { al[row] = s; ar[row] = t; }
}

// ---------------------------------------------------------------------------
// Edge scatter (softmax without max-shift; normalization deferred)
// ---------------------------------------------------------------------------
__global__ void edge_scatter_f(const int* __restrict__ src, const int* __restrict__ dst, int E,
                               const float* __restrict__ al, const float* __restrict__ ar,
                               float* __restrict__ ssum,
                               const float* __restrict__ Z, float* __restrict__ H)
{
    int gt = blockIdx.x * blockDim.x + threadIdx.x;
    int e = gt >> 5, lane = gt & 31;
    if (e >= E) return;
    int s = src[e], d = dst[e];
    float w = expf(leaky_f(al[s] + ar[d]));
    if (lane == 0) atomicAdd(&ssum[d], w);
    float4 z = reinterpret_cast<const float4*>(Z + (size_t)s * HIDC)[lane];
    redv4(H + (size_t)d * HIDC + lane * 4, z.x * w, z.y * w, z.z * w, z.w * w);
}

// H = elu(H/(sum+1e-16) + b), and emit bf16 planes (pairs)
__global__ void bias_elu_split(float* __restrict__ H, const float* __restrict__ ssum,
                               const float* __restrict__ b,
                               uint32_t* __restrict__ Hh, uint32_t* __restrict__ Hl, int n)
{
    int i = blockIdx.x * blockDim.x + threadIdx.x;
    if (i >= n * 64) return;
    int r = i >> 6, p = i & 63;
    float inv = 1.f / (ssum[r] + 1e-16f);
    float2 v = reinterpret_cast<float2*>(H)[i];
    float v0 = v.x * inv + b[2 * p];
    float v1 = v.y * inv + b[2 * p + 1];
    v0 = v0 > 0.f ? v0 : expm1f(v0);
    v1 = v1 > 0.f ? v1 : expm1f(v1);
    reinterpret_cast<float2*>(H)[i] = make_float2(v0, v1);
    uint32_t h, l; split2(v0, v1, h, l);
    Hh[i] = h; Hl[i] = l;
}

// GRU gates + relu; X updated in place; emit planes
__global__ void gru_gate_split(const float* __restrict__ GI, const float* __restrict__ GH,
                               float* __restrict__ X,
                               uint32_t* __restrict__ Xh, uint32_t* __restrict__ Xl, int N)
{
    int i = blockIdx.x * blockDim.x + threadIdx.x;
    if (i >= N * 64) return;
    int n = i >> 6, p = i & 63;
    const float* gi = GI + (size_t)n * H3C;
    const float* gh = GH + (size_t)n * H3C;
    float o01[2];
    #pragma unroll
    for (int q = 0; q < 2; q++) {
        int c = 2 * p + q;
        float r  = 1.f / (1.f + expf(-(gi[c]       + gh[c])));
        float z  = 1.f / (1.f + expf(-(gi[c + 128] + gh[c + 128])));
        float nn = tanhf(gi[c + 256] + r * gh[c + 256]);
        float o  = (1.f - z) * nn + z * X[(size_t)n * HIDC + c];
        o01[q] = fmaxf(o, 0.f);
        X[(size_t)n * HIDC + c] = o01[q];
    }
    uint32_t h, l; split2(o01[0], o01[1], h, l);
    Xh[i] = h; Xl[i] = l;
}

// ---------------------------------------------------------------------------
// Readout kernels
// ---------------------------------------------------------------------------
__global__ void node_scatter_sum(const int* __restrict__ batch, const float* __restrict__ X,
                                 float* __restrict__ OUT, int N)
{
    int gt = blockIdx.x * blockDim.x + threadIdx.x;
    int n = gt >> 5, lane = gt & 31;
    if (n >= N) return;
    int b = batch[n];
    float4 v = reinterpret_cast<const float4*>(X + (size_t)n * HIDC)[lane];
    redv4(OUT + (size_t)b * HIDC + lane * 4, v.x, v.y, v.z, v.w);
}

// OUT = relu(OUT); emit planes
__global__ void relu_split(float* __restrict__ OUT, uint32_t* __restrict__ Oh,
                           uint32_t* __restrict__ Ol, int n)
{
    int i = blockIdx.x * blockDim.x + threadIdx.x;
    if (i >= n * 64) return;
    float2 v = reinterpret_cast<float2*>(OUT)[i];
    v.x = fmaxf(v.x, 0.f); v.y = fmaxf(v.y, 0.f);
    reinterpret_cast<float2*>(OUT)[i] = v;
    uint32_t h, l; split2(v.x, v.y, h, l);
    Oh[i] = h; Ol[i] = l;
}

__global__ void node_scatter_f(const int* __restrict__ batch, int N,
                               const float* __restrict__ asrc, const float* __restrict__ adst,
                               float* __restrict__ ssum,
                               const float* __restrict__ XT, float* __restrict__ H2)
{
    int gt = blockIdx.x * blockDim.x + threadIdx.x;
    int n = gt >> 5, lane = gt & 31;
    if (n >= N) return;
    int b = batch[n];
    float w = expf(leaky_f(asrc[n] + adst[b]));
    if (lane == 0) atomicAdd(&ssum[b], w);
    float4 v = reinterpret_cast<const float4*>(XT + (size_t)n * HIDC)[lane];
    redv4(H2 + (size_t)b * HIDC + lane * 4, v.x * w, v.y * w, v.z * w, v.w * w);
}

__global__ void final_out(const float* __restrict__ OUT, const float* __restrict__ W2,
                          const float* __restrict__ b2, float* __restrict__ out, int G)
{
    int gt = blockIdx.x * blockDim.x + threadIdx.x;
    int g = gt >> 5, lane = gt & 31;
    if (g >= G) return;
    const float* a = OUT + (size_t)g * HIDC;
    float s = 0.f;
    #pragma unroll
    for (int i = 0; i < 4; i++) s += a[lane + i * 32] * W2[lane + i * 32];
    #pragma unroll
    for (int off = 16; off; off >>= 1) s += __shfl_xor_sync(0xFFFFFFFFu, s, off);
    if (lane == 0) out[g] = s + b2[0];
}

// ---------------------------------------------------------------------------
// Host
// ---------------------------------------------------------------------------
static inline int cdiv(int a, int b) { return (a + b - 1) / b; }

#define SYM(var, sym) cudaGetSymbolAddress((void**)&var, sym)

extern "C" void kernel_launch(void* const* d_in, const int* in_sizes, int n_in,
                              void* d_out, int out_size)
{
    const float* x      = (const float*)d_in[0];
    const int*   ei     = (const int*)  d_in[1];
    const int*   batch  = (const int*)  d_in[2];
    const float* W1     = (const float*)d_in[3];
    const float* b1     = (const float*)d_in[4];
    const float* Wg1    = (const float*)d_in[5];
    const float* att_l  = (const float*)d_in[6];
    const float* att_r  = (const float*)d_in[7];
    const float* Wg2    = (const float*)d_in[8];
    const float* bg     = (const float*)d_in[9];
    const float* Wih0   = (const float*)d_in[10];
    const float* Whh0   = (const float*)d_in[11];
    const float* bih0   = (const float*)d_in[12];
    const float* bhh0   = (const float*)d_in[13];
    const float* Wa     = (const float*)d_in[14];
    const float* asrc_a = (const float*)d_in[15];
    const float* adst_a = (const float*)d_in[16];
    const float* ba     = (const float*)d_in[17];
    const float* Wih_a  = (const float*)d_in[18];
    const float* Whh_a  = (const float*)d_in[19];
    const float* bih_a  = (const float*)d_in[20];
    const float* bhh_a  = (const float*)d_in[21];
    const float* Wm     = (const float*)d_in[22];
    const float* asrc_m = (const float*)d_in[23];
    const float* adst_m = (const float*)d_in[24];
    const float* bm     = (const float*)d_in[25];
    const float* Wih_m  = (const float*)d_in[26];
    const float* Whh_m  = (const float*)d_in[27];
    const float* bih_m  = (const float*)d_in[28];
    const float* bhh_m  = (const float*)d_in[29];
    const float* W2     = (const float*)d_in[30];
    const float* b2     = (const float*)d_in[31];
    float* out = (float*)d_out;

    const int N = in_sizes[0] / 64;
    const int E = in_sizes[1] / 2;
    const int G = out_size;
    const int* src = ei;
    const int* dst = ei + E;

    static int smem_set = 0;
    if (!smem_set) {
        cudaFuncSetAttribute(gemm_p, cudaFuncAttributeMaxDynamicSharedMemorySize, GEMM_SMEM);
        smem_set = 1;
    }

    float *X, *Z, *H, *GI, *GH, *al, *ar, *sum, *cE, *Wg1p;
    float *OUT, *OT, *H2, *GI2, *GH2, *ad;
    SYM(X, g_X); SYM(Z, g_Z); SYM(H, g_H); SYM(GI, g_GI); SYM(GH, g_GH);
    SYM(al, g_al); SYM(ar, g_ar); SYM(sum, g_sum);
    SYM(cE, g_cE); SYM(Wg1p, g_Wg1p);
    SYM(OUT, g_OUT); SYM(OT, g_OT); SYM(H2, g_H2);
    SYM(GI2, g_GI2); SYM(GH2, g_GH2); SYM(ad, g_ad);

    uint32_t *xih, *xil, *XAh, *XAl, *HAh, *HAl, *OAh, *OAl, *H2Ah, *H2Al;
    SYM(xih, g_xih); SYM(xil, g_xil);
    SYM(XAh, g_XAh); SYM(XAl, g_XAl); SYM(HAh, g_HAh); SYM(HAl, g_HAl);
    SYM(OAh, g_OAh); SYM(OAl, g_OAl); SYM(H2Ah, g_H2Ah); SYM(H2Al, g_H2Al);

    uint32_t *wW1h,*wW1l,*wWg1h,*wWg1l,*wWg2h,*wWg2l,*wWih0h,*wWih0l,*wWhh0h,*wWhh0l;
    uint32_t *wWah,*wWal,*wWihah,*wWihal,*wWhhah,*wWhhal,*wWmh,*wWml,*wWihmh,*wWihml,*wWhhmh,*wWhhml;
    SYM(wW1h, g_wW1h); SYM(wW1l, g_wW1l);
    SYM(wWg1h, g_wWg1h); SYM(wWg1l, g_wWg1l);
    SYM(wWg2h, g_wWg2h); SYM(wWg2l, g_wWg2l);
    SYM(wWih0h, g_wWih0h); SYM(wWih0l, g_wWih0l);
    SYM(wWhh0h, g_wWhh0h); SYM(wWhh0l, g_wWhh0l);
    SYM(wWah, g_wWah); SYM(wWal, g_wWal);
    SYM(wWihah, g_wWihah); SYM(wWihal, g_wWihal);
    SYM(wWhhah, g_wWhhah); SYM(wWhhal, g_wWhhal);
    SYM(wWmh, g_wWmh); SYM(wWml, g_wWml);
    SYM(wWihmh, g_wWihmh); SYM(wWihml, g_wWihml);
    SYM(wWhhmh, g_wWhhmh); SYM(wWhhml, g_wWhhml);

    auto split = [&](const float* A, uint32_t* hi, uint32_t* lo, int pairs) {
        split_mat<<<cdiv(pairs, 256), 256>>>(A, hi, lo, pairs);
    };
    auto gemm = [&](const uint32_t* Ah, const uint32_t* Al,
                    const uint32_t* Wh, const uint32_t* Wl,
                    const float* bias, float* C, uint32_t* Chi, uint32_t* Clo,
                    int n, int mm, int k, int act) {
        dim3 grid(mm / 128, cdiv(n, 128));
        gemm_p<<<grid, 256, GEMM_SMEM>>>(Ah, Al, Wh, Wl, bias, C, Chi, Clo, n, mm, k, act);
    };

    const int T256_NC  = cdiv(N * HIDC, 256);
    const int T256_NP  = cdiv(N * 64, 256);
    const int WARP_E   = cdiv(E * 32, 256);
    const int WARP_N   = cdiv(N * 32, 256);

    auto message_pass = [&](const float* bias_vec) {
        fill_sum_H   <<<T256_NC, 256>>>(sum, H, N);
        edge_scatter_f<<<WARP_E, 256>>>(src, dst, E, al, ar, sum, Z, H);
        bias_elu_split<<<T256_NP, 256>>>(H, sum, bias_vec, HAh, HAl, N);
    };

    // ---- weight prep ----
    comp_cedge<<<1, 128>>>(Wg1, cE);
    pack_wg1<<<64, 256>>>(Wg1, Wg1p);
    split(W1,   wW1h,   wW1l,   128 * 32);
    split(Wg1p, wWg1h,  wWg1l,  128 * 64);
    split(Wg2,  wWg2h,  wWg2l,  128 * 64);
    split(Wih0, wWih0h, wWih0l, 384 * 64);
    split(Whh0, wWhh0h, wWhh0l, 384 * 64);
    split(Wa,   wWah,   wWal,   2 * 128 * 64);
    split(Wih_a, wWihah, wWihal, 2 * 384 * 64);
    split(Whh_a, wWhhah, wWhhal, 2 * 384 * 64);
    split(Wm,   wWmh,   wWml,   128 * 64);
    split(Wih_m, wWihmh, wWihml, 384 * 64);
    split(Whh_m, wWhhmh, wWhhml, 384 * 64);

    // ---- Stage 0: X = leaky(x @ W1^T + b1), planes emitted ----
    split(x, xih, xil, N * 32);
    gemm(xih, xil, wW1h, wW1l, b1, X, XAh, XAl, N, 128, 64, 1);

    // ---- Stage 1: GATEConv + GRU ----
    gemm(XAh, XAl, wWg1h, wWg1l, cE, H, nullptr, nullptr, N, 128, 128, 1);
    rowdot_ab<<<WARP_N, 256>>>(H, att_l, X, att_r, al, ar, N);
    gemm(XAh, XAl, wWg2h, wWg2l, nullptr, Z, nullptr, nullptr, N, 128, 128, 0);
    message_pass(bg);
    gemm(HAh, HAl, wWih0h, wWih0l, bih0, GI, nullptr, nullptr, N, 384, 128, 0);
    gemm(XAh, XAl, wWhh0h, wWhh0l, bhh0, GH, nullptr, nullptr, N, 384, 128, 0);
    gru_gate_split<<<T256_NP, 256>>>(GI, GH, X, XAh, XAl, N);

    // ---- Stage 2: 2 x (GATConv + GRU) ----
    for (int l = 0; l < 2; l++) {
        gemm(XAh, XAl, wWah + (size_t)l * 128 * 64, wWal + (size_t)l * 128 * 64,
             nullptr, Z, nullptr, nullptr, N, 128, 128, 0);
        rowdot2<<<WARP_N, 256>>>(Z, asrc_a + l * HIDC, adst_a + l * HIDC, al, ar, N);
        message_pass(ba + l * HIDC);
        gemm(HAh, HAl, wWihah + (size_t)l * 384 * 64, wWihal + (size_t)l * 384 * 64,
             bih_a + l * H3C, GI, nullptr, nullptr, N, 384, 128, 0);
        gemm(XAh, XAl, wWhhah + (size_t)l * 384 * 64, wWhhal + (size_t)l * 384 * 64,
             bhh_a + l * H3C, GH, nullptr, nullptr, N, 384, 128, 0);
        gru_gate_split<<<T256_NP, 256>>>(GI, GH, X, XAh, XAl, N);
    }

    // ---- Stage 3: attentive readout ----
    const int T256_GC = cdiv(G * HIDC, 256);
    const int T256_GP = cdiv(G * 64, 256);
    const int WARP_G  = cdiv(G * 32, 256);

    fill_f32<<<T256_GC, 256>>>(OUT, 0.f, G * HIDC);
    node_scatter_sum<<<WARP_N, 256>>>(batch, X, OUT, N);
    relu_split<<<T256_GP, 256>>>(OUT, OAh, OAl, G);

    gemm(XAh, XAl, wWmh, wWml, nullptr, Z, nullptr, nullptr, N, 128, 128, 0);
    rowdot<<<WARP_N, 256>>>(Z, asrc_m, al, N);

    for (int t = 0; t < 3; t++) {
        gemm(OAh, OAl, wWmh, wWml, nullptr, OT, nullptr, nullptr, G, 128, 128, 0);
        rowdot<<<WARP_G, 256>>>(OT, adst_m, ad, G);
        fill_sum_H<<<T256_GC, 256>>>(sum, H2, G);
        node_scatter_f<<<WARP_N, 256>>>(batch, N, al, ad, sum, Z, H2);
        bias_elu_split<<<T256_GP, 256>>>(H2, sum, bm, H2Ah, H2Al, G);
        gemm(H2Ah, H2Al, wWihmh, wWihml, bih_m, GI2, nullptr, nullptr, G, 384, 128, 0);
        gemm(OAh, OAl, wWhhmh, wWhhml, bhh_m, GH2, nullptr, nullptr, G, 384, 128, 0);
        gru_gate_split<<<T256_GP, 256>>>(GI2, GH2, OUT, OAh, OAl, G);
    }

    final_out<<<WARP_G, 256>>>(OUT, W2, b2, out, G);
}

// round 12
// speedup vs baseline: 2.7770x; 1.0848x over previous
#include <cuda_runtime.h>
#include <cuda_bf16.h>
#include <math.h>
#include <stdint.h>

// ---------------------------------------------------------------------------
// Problem constants
// ---------------------------------------------------------------------------
#define NMAX   50000
#define EMAX   800000
#define GMAX   1024
#define HIDC   128
#define H3C    384
#define NEGS   0.01f

// ---------------------------------------------------------------------------
// Scratch (device globals; no allocation allowed)
// ---------------------------------------------------------------------------
__device__ float g_X  [(size_t)NMAX * HIDC];
__device__ float g_Z  [(size_t)NMAX * HIDC];
__device__ float g_H  [(size_t)NMAX * HIDC];
__device__ float g_GI [(size_t)NMAX * H3C];
__device__ float g_GH [(size_t)NMAX * H3C];
__device__ float g_al [NMAX];
__device__ float g_ar [NMAX];
__device__ float g_sum[NMAX];
__device__ float g_cE [HIDC];
__device__ float g_Wg1p[HIDC * HIDC];
__device__ float g_OUT [GMAX * HIDC];
__device__ float g_OT  [GMAX * HIDC];
__device__ float g_H2  [GMAX * HIDC];
__device__ float g_GI2 [GMAX * H3C];
__device__ float g_GH2 [GMAX * H3C];
__device__ float g_ad  [GMAX];

// bf16 hi/lo planes (packed pairs, u32 = 2 bf16)
__device__ uint32_t g_xih[(size_t)NMAX * 32], g_xil[(size_t)NMAX * 32];
__device__ uint32_t g_XAh[(size_t)NMAX * 64], g_XAl[(size_t)NMAX * 64];
__device__ uint32_t g_HAh[(size_t)NMAX * 64], g_HAl[(size_t)NMAX * 64];
__device__ uint32_t g_OAh[GMAX * 64],  g_OAl[GMAX * 64];
__device__ uint32_t g_H2Ah[GMAX * 64], g_H2Al[GMAX * 64];
// weight planes
__device__ uint32_t g_wW1h[128 * 32],  g_wW1l[128 * 32];
__device__ uint32_t g_wWg1h[128 * 64], g_wWg1l[128 * 64];
__device__ uint32_t g_wWg2h[128 * 64], g_wWg2l[128 * 64];
__device__ uint32_t g_wWih0h[384 * 64], g_wWih0l[384 * 64];
__device__ uint32_t g_wWhh0h[384 * 64], g_wWhh0l[384 * 64];
__device__ uint32_t g_wWah[2 * 128 * 64], g_wWal[2 * 128 * 64];
__device__ uint32_t g_wWihah[2 * 384 * 64], g_wWihal[2 * 384 * 64];
__device__ uint32_t g_wWhhah[2 * 384 * 64], g_wWhhal[2 * 384 * 64];
__device__ uint32_t g_wWmh[128 * 64],  g_wWml[128 * 64];
__device__ uint32_t g_wWihmh[384 * 64], g_wWihml[384 * 64];
__device__ uint32_t g_wWhhmh[384 * 64], g_wWhhml[384 * 64];

// ---------------------------------------------------------------------------
// Helpers
// ---------------------------------------------------------------------------
__device__ __forceinline__ float leaky_f(float v) { return v >= 0.f ? v : NEGS * v; }

__device__ __forceinline__ void redv4(float* p, float a, float b, float c, float d) {
    asm volatile("red.global.add.v4.f32 [%0], {%1,%2,%3,%4};"
                 :: "l"(p), "f"(a), "f"(b), "f"(c), "f"(d) : "memory");
}

__device__ __forceinline__ void split2(float a, float b, uint32_t& hi, uint32_t& lo) {
    __nv_bfloat16 ah = __float2bfloat16_rn(a);
    __nv_bfloat16 bh = __float2bfloat16_rn(b);
    __nv_bfloat162 h; h.x = ah; h.y = bh;
    hi = *reinterpret_cast<uint32_t*>(&h);
    __nv_bfloat162 l;
    l.x = __float2bfloat16_rn(a - __bfloat162float(ah));
    l.y = __float2bfloat16_rn(b - __bfloat162float(bh));
    lo = *reinterpret_cast<uint32_t*>(&l);
}

__device__ __forceinline__ void mma_bf16(float c[4], const uint32_t a[4], const uint32_t b[2]) {
    asm volatile("mma.sync.aligned.m16n8k16.row.col.f32.bf16.bf16.f32 "
        "{%0,%1,%2,%3}, {%4,%5,%6,%7}, {%8,%9}, {%0,%1,%2,%3};"
        : "+f"(c[0]), "+f"(c[1]), "+f"(c[2]), "+f"(c[3])
        : "r"(a[0]), "r"(a[1]), "r"(a[2]), "r"(a[3]), "r"(b[0]), "r"(b[1]));
}

__device__ __forceinline__ void cp16(uint32_t* s, const uint32_t* g) {
    uint32_t sa = (uint32_t)__cvta_generic_to_shared(s);
    asm volatile("cp.async.cg.shared.global [%0], [%1], 16;" :: "r"(sa), "l"(g));
}

// ---------------------------------------------------------------------------
// Split matrix into bf16 hi/lo packed planes (weights + input x only)
// ---------------------------------------------------------------------------
__global__ void split_mat(const float* __restrict__ A, uint32_t* __restrict__ hi,
                          uint32_t* __restrict__ lo, int pairs)
{
    int i = blockIdx.x * blockDim.x + threadIdx.x;
    if (i >= pairs) return;
    float2 v = reinterpret_cast<const float2*>(A)[i];
    uint32_t h, l;
    split2(v.x, v.y, h, l);
    hi[i] = h; lo[i] = l;
}

// ---------------------------------------------------------------------------
// Plane GEMM: C[N,M] = act(A[N,K] * W[M,K]^T + bias); optional plane output
// (Chi/Clo, only valid when M == 128). BM=64, BN=128, full K resident.
// smem = 104 KB -> 2 CTAs per SM (load/compute overlap across CTAs).
// 256 threads = 8 warps (2x4), warp tile 32x32.
// ---------------------------------------------------------------------------
#define SP 68
#define GEMM_SMEM ((2 * 64 + 2 * 128) * SP * 4)

__global__ __launch_bounds__(256)
void gemm_p(const uint32_t* __restrict__ Ah, const uint32_t* __restrict__ Al,
            const uint32_t* __restrict__ Wh, const uint32_t* __restrict__ Wl,
            const float* __restrict__ bias, float* __restrict__ C,
            uint32_t* __restrict__ Chi, uint32_t* __restrict__ Clo,
            int N, int M, int K, int act)
{
    extern __shared__ uint32_t smem[];
    uint32_t* sAh = smem;
    uint32_t* sAl = smem + 64 * SP;
    uint32_t* sWh = smem + 2 * 64 * SP;
    uint32_t* sWl = smem + 2 * 64 * SP + 128 * SP;

    const int tid  = threadIdx.x;
    const int lane = tid & 31;
    const int warp = tid >> 5;
    const int gID  = lane >> 2;
    const int tig  = lane & 3;
    const int row0 = blockIdx.y * 64;
    const int col0 = blockIdx.x * 128;
    const int warpM = (warp >> 2) * 32;
    const int warpN = (warp & 3) * 32;

    const int kp  = K >> 1;          // u32 per row
    const int kp4 = kp >> 2;         // 16B segs per row
    const int sh  = (kp4 == 16) ? 4 : 3;
    const int msk = kp4 - 1;

    // A tile: 64 rows (guarded by N)
    for (int s = tid; s < 64 * kp4; s += 256) {
        int r = s >> sh, c = (s & msk) << 2;
        int gr = row0 + r;
        if (gr < N) {
            cp16(&sAh[r * SP + c], Ah + (size_t)gr * kp + c);
            cp16(&sAl[r * SP + c], Al + (size_t)gr * kp + c);
        }
    }
    // W tile: 128 rows (M multiple of 128)
    for (int s = tid; s < 128 * kp4; s += 256) {
        int r = s >> sh, c = (s & msk) << 2;
        int gw = col0 + r;
        cp16(&sWh[r * SP + c], Wh + (size_t)gw * kp + c);
        cp16(&sWl[r * SP + c], Wl + (size_t)gw * kp + c);
    }
    asm volatile("cp.async.commit_group;");
    asm volatile("cp.async.wait_group 0;");
    __syncthreads();

    float c[2][4][4];
    #pragma unroll
    for (int i = 0; i < 2; i++)
        #pragma unroll
        for (int j = 0; j < 4; j++)
            #pragma unroll
            for (int q = 0; q < 4; q++) c[i][j][q] = 0.f;

    const int nks = K >> 4;
    for (int ks = 0; ks < nks; ks++) {
        const int pb = ks * 8;
        uint32_t ah[2][4], alr[2][4], bh[4][2], blr[4][2];
        #pragma unroll
        for (int i = 0; i < 2; i++) {
            int b0 = (warpM + i * 16 + gID) * SP + pb + tig;
            int b8 = b0 + 8 * SP;
            ah[i][0] = sAh[b0];     ah[i][1] = sAh[b8];
            ah[i][2] = sAh[b0 + 4]; ah[i][3] = sAh[b8 + 4];
            alr[i][0] = sAl[b0];     alr[i][1] = sAl[b8];
            alr[i][2] = sAl[b0 + 4]; alr[i][3] = sAl[b8 + 4];
        }
        #pragma unroll
        for (int j = 0; j < 4; j++) {
            int wb = (warpN + j * 8 + gID) * SP + pb + tig;
            bh[j][0] = sWh[wb]; bh[j][1] = sWh[wb + 4];
            blr[j][0] = sWl[wb]; blr[j][1] = sWl[wb + 4];
        }
        #pragma unroll
        for (int i = 0; i < 2; i++)
            #pragma unroll
            for (int j = 0; j < 4; j++) mma_bf16(c[i][j], ah[i], bh[j]);
        #pragma unroll
        for (int i = 0; i < 2; i++)
            #pragma unroll
            for (int j = 0; j < 4; j++) mma_bf16(c[i][j], alr[i], bh[j]);
        #pragma unroll
        for (int i = 0; i < 2; i++)
            #pragma unroll
            for (int j = 0; j < 4; j++) mma_bf16(c[i][j], ah[i], blr[j]);
    }

    const int mp = M >> 1;
    #pragma unroll
    for (int i = 0; i < 2; i++) {
        int r_lo = row0 + warpM + i * 16 + gID;
        int r_hi = r_lo + 8;
        #pragma unroll
        for (int j = 0; j < 4; j++) {
            int cc = col0 + warpN + j * 8 + tig * 2;
            float b0 = bias ? bias[cc] : 0.f;
            float b1 = bias ? bias[cc + 1] : 0.f;
            float v0 = c[i][j][0] + b0, v1 = c[i][j][1] + b1;
            float v2 = c[i][j][2] + b0, v3 = c[i][j][3] + b1;
            if (act == 1) { v0 = leaky_f(v0); v1 = leaky_f(v1); v2 = leaky_f(v2); v3 = leaky_f(v3); }
            if (r_lo < N) {
                C[(size_t)r_lo * M + cc]     = v0;
                C[(size_t)r_lo * M + cc + 1] = v1;
                if (Chi) {
                    uint32_t h, l; split2(v0, v1, h, l);
                    Chi[(size_t)r_lo * mp + (cc >> 1)] = h;
                    Clo[(size_t)r_lo * mp + (cc >> 1)] = l;
                }
            }
            if (r_hi < N) {
                C[(size_t)r_hi * M + cc]     = v2;
                C[(size_t)r_hi * M + cc + 1] = v3;
                if (Chi) {
                    uint32_t h, l; split2(v2, v3, h, l);
                    Chi[(size_t)r_hi * mp + (cc >> 1)] = h;
                    Clo[(size_t)r_hi * mp + (cc >> 1)] = l;
                }
            }
        }
    }
}

// ---------------------------------------------------------------------------
// Small elementwise / utility kernels
// ---------------------------------------------------------------------------
__global__ void fill_f32(float* p, float v, int n) {
    int i = blockIdx.x * blockDim.x + threadIdx.x;
    if (i < n) p[i] = v;
}

__global__ void fill_sum_H(float* __restrict__ ssum, float* __restrict__ H, int n) {
    int i = blockIdx.x * blockDim.x + threadIdx.x;
    if (i < n) ssum[i] = 0.f;
    if (i < n * HIDC) H[i] = 0.f;
}

__global__ void comp_cedge(const float* __restrict__ Wg1, float* __restrict__ cE) {
    int m = threadIdx.x;
    if (m < HIDC) {
        float s = 0.f;
        #pragma unroll
        for (int j = 0; j < 25; j++) s += Wg1[(size_t)m * 153 + 128 + j];
        cE[m] = s;
    }
}

__global__ void pack_wg1(const float* __restrict__ Wg1, float* __restrict__ out) {
    int i = blockIdx.x * blockDim.x + threadIdx.x;
    if (i < HIDC * HIDC) {
        int r = i >> 7, c = i & 127;
        out[i] = Wg1[(size_t)r * 153 + c];
    }
}

__global__ void rowdot(const float* __restrict__ A, const float* __restrict__ v,
                       float* __restrict__ out, int N)
{
    int gt = blockIdx.x * blockDim.x + threadIdx.x;
    int row = gt >> 5, lane = gt & 31;
    if (row >= N) return;
    const float* a = A + (size_t)row * HIDC;
    float s = 0.f;
    #pragma unroll
    for (int i = 0; i < 4; i++) s += a[lane + i * 32] * v[lane + i * 32];
    #pragma unroll
    for (int off = 16; off; off >>= 1) s += __shfl_xor_sync(0xFFFFFFFFu, s, off);
    if (lane == 0) out[row] = s;
}

__global__ void rowdot2(const float* __restrict__ Z, const float* __restrict__ va,
                        const float* __restrict__ vb, float* __restrict__ al,
                        float* __restrict__ ar, int N)
{
    int gt = blockIdx.x * blockDim.x + threadIdx.x;
    int row = gt >> 5, lane = gt & 31;
    if (row >= N) return;
    const float* a = Z + (size_t)row * HIDC;
    float s = 0.f, t = 0.f;
    #pragma unroll
    for (int i = 0; i < 4; i++) {
        float z = a[lane + i * 32];
        s += z * va[lane + i * 32];
        t += z * vb[lane + i * 32];
    }
    #pragma unroll
    for (int off = 16; off; off >>= 1) {
        s += __shfl_xor_sync(0xFFFFFFFFu, s, off);
        t += __shfl_xor_sync(0xFFFFFFFFu, t, off);
    }
    if (lane == 0) { al[row] = s; ar[row] = t; }
}

__global__ void rowdot_ab(const float* __restrict__ A, const float* __restrict__ va,
                          const float* __restrict__ B, const float* __restrict__ vb,
                          float* __restrict__ al, float* __restrict__ ar, int N)
{
    int gt = blockIdx.x * blockDim.x + threadIdx.x;
    int row = gt >> 5, lane = gt & 31;
    if (row >= N) return;
    const float* a = A + (size_t)row * HIDC;
    const float* b = B + (size_t)row * HIDC;
    float s = 0.f, t = 0.f;
    #pragma unroll
    for (int i = 0; i < 4; i++) {
        s += a[lane + i * 32] * va[lane + i * 32];
        t += b[lane + i * 32] * vb[lane + i * 32];
    }
    #pragma unroll
    for (int off = 16; off; off >>= 1) {
        s += __shfl_xor_sync(0xFFFFFFFFu, s, off);
        t += __shfl_xor_sync(0xFFFFFFFFu, t, off);
    }
    if (lane == 0) { al[row] = s; ar[row] = t; }
}

// ---------------------------------------------------------------------------
// Edge scatter (softmax without max-shift; normalization deferred)
// ---------------------------------------------------------------------------
__global__ void edge_scatter_f(const int* __restrict__ src, const int* __restrict__ dst, int E,
                               const float* __restrict__ al, const float* __restrict__ ar,
                               float* __restrict__ ssum,
                               const float* __restrict__ Z, float* __restrict__ H)
{
    int gt = blockIdx.x * blockDim.x + threadIdx.x;
    int e = gt >> 5, lane = gt & 31;
    if (e >= E) return;
    int s = src[e], d = dst[e];
    float w = expf(leaky_f(al[s] + ar[d]));
    if (lane == 0) atomicAdd(&ssum[d], w);
    float4 z = reinterpret_cast<const float4*>(Z + (size_t)s * HIDC)[lane];
    redv4(H + (size_t)d * HIDC + lane * 4, z.x * w, z.y * w, z.z * w, z.w * w);
}

__global__ void bias_elu_split(float* __restrict__ H, const float* __restrict__ ssum,
                               const float* __restrict__ b,
                               uint32_t* __restrict__ Hh, uint32_t* __restrict__ Hl, int n)
{
    int i = blockIdx.x * blockDim.x + threadIdx.x;
    if (i >= n * 64) return;
    int r = i >> 6, p = i & 63;
    float inv = 1.f / (ssum[r] + 1e-16f);
    float2 v = reinterpret_cast<float2*>(H)[i];
    float v0 = v.x * inv + b[2 * p];
    float v1 = v.y * inv + b[2 * p + 1];
    v0 = v0 > 0.f ? v0 : expm1f(v0);
    v1 = v1 > 0.f ? v1 : expm1f(v1);
    reinterpret_cast<float2*>(H)[i] = make_float2(v0, v1);
    uint32_t h, l; split2(v0, v1, h, l);
    Hh[i] = h; Hl[i] = l;
}

__global__ void gru_gate_split(const float* __restrict__ GI, const float* __restrict__ GH,
                               float* __restrict__ X,
                               uint32_t* __restrict__ Xh, uint32_t* __restrict__ Xl, int N)
{
    int i = blockIdx.x * blockDim.x + threadIdx.x;
    if (i >= N * 64) return;
    int n = i >> 6, p = i & 63;
    const float* gi = GI + (size_t)n * H3C;
    const float* gh = GH + (size_t)n * H3C;
    float o01[2];
    #pragma unroll
    for (int q = 0; q < 2; q++) {
        int c = 2 * p + q;
        float r  = 1.f / (1.f + expf(-(gi[c]       + gh[c])));
        float z  = 1.f / (1.f + expf(-(gi[c + 128] + gh[c + 128])));
        float nn = tanhf(gi[c + 256] + r * gh[c + 256]);
        float o  = (1.f - z) * nn + z * X[(size_t)n * HIDC + c];
        o01[q] = fmaxf(o, 0.f);
        X[(size_t)n * HIDC + c] = o01[q];
    }
    uint32_t h, l; split2(o01[0], o01[1], h, l);
    Xh[i] = h; Xl[i] = l;
}

// ---------------------------------------------------------------------------
// Readout kernels
// ---------------------------------------------------------------------------
__global__ void node_scatter_sum(const int* __restrict__ batch, const float* __restrict__ X,
                                 float* __restrict__ OUT, int N)
{
    int gt = blockIdx.x * blockDim.x + threadIdx.x;
    int n = gt >> 5, lane = gt & 31;
    if (n >= N) return;
    int b = batch[n];
    float4 v = reinterpret_cast<const float4*>(X + (size_t)n * HIDC)[lane];
    redv4(OUT + (size_t)b * HIDC + lane * 4, v.x, v.y, v.z, v.w);
}

__global__ void relu_split(float* __restrict__ OUT, uint32_t* __restrict__ Oh,
                           uint32_t* __restrict__ Ol, int n)
{
    int i = blockIdx.x * blockDim.x + threadIdx.x;
    if (i >= n * 64) return;
    float2 v = reinterpret_cast<float2*>(OUT)[i];
    v.x = fmaxf(v.x, 0.f); v.y = fmaxf(v.y, 0.f);
    reinterpret_cast<float2*>(OUT)[i] = v;
    uint32_t h, l; split2(v.x, v.y, h, l);
    Oh[i] = h; Ol[i] = l;
}

__global__ void node_scatter_f(const int* __restrict__ batch, int N,
                               const float* __restrict__ asrc, const float* __restrict__ adst,
                               float* __restrict__ ssum,
                               const float* __restrict__ XT, float* __restrict__ H2)
{
    int gt = blockIdx.x * blockDim.x + threadIdx.x;
    int n = gt >> 5, lane = gt & 31;
    if (n >= N) return;
    int b = batch[n];
    float w = expf(leaky_f(asrc[n] + adst[b]));
    if (lane == 0) atomicAdd(&ssum[b], w);
    float4 v = reinterpret_cast<const float4*>(XT + (size_t)n * HIDC)[lane];
    redv4(H2 + (size_t)b * HIDC + lane * 4, v.x * w, v.y * w, v.z * w, v.w * w);
}

__global__ void final_out(const float* __restrict__ OUT, const float* __restrict__ W2,
                          const float* __restrict__ b2, float* __restrict__ out, int G)
{
    int gt = blockIdx.x * blockDim.x + threadIdx.x;
    int g = gt >> 5, lane = gt & 31;
    if (g >= G) return;
    const float* a = OUT + (size_t)g * HIDC;
    float s = 0.f;
    #pragma unroll
    for (int i = 0; i < 4; i++) s += a[lane + i * 32] * W2[lane + i * 32];
    #pragma unroll
    for (int off = 16; off; off >>= 1) s += __shfl_xor_sync(0xFFFFFFFFu, s, off);
    if (lane == 0) out[g] = s + b2[0];
}

// ---------------------------------------------------------------------------
// Host
// ---------------------------------------------------------------------------
static inline int cdiv(int a, int b) { return (a + b - 1) / b; }

#define SYM(var, sym) cudaGetSymbolAddress((void**)&var, sym)

extern "C" void kernel_launch(void* const* d_in, const int* in_sizes, int n_in,
                              void* d_out, int out_size)
{
    const float* x      = (const float*)d_in[0];
    const int*   ei     = (const int*)  d_in[1];
    const int*   batch  = (const int*)  d_in[2];
    const float* W1     = (const float*)d_in[3];
    const float* b1     = (const float*)d_in[4];
    const float* Wg1    = (const float*)d_in[5];
    const float* att_l  = (const float*)d_in[6];
    const float* att_r  = (const float*)d_in[7];
    const float* Wg2    = (const float*)d_in[8];
    const float* bg     = (const float*)d_in[9];
    const float* Wih0   = (const float*)d_in[10];
    const float* Whh0   = (const float*)d_in[11];
    const float* bih0   = (const float*)d_in[12];
    const float* bhh0   = (const float*)d_in[13];
    const float* Wa     = (const float*)d_in[14];
    const float* asrc_a = (const float*)d_in[15];
    const float* adst_a = (const float*)d_in[16];
    const float* ba     = (const float*)d_in[17];
    const float* Wih_a  = (const float*)d_in[18];
    const float* Whh_a  = (const float*)d_in[19];
    const float* bih_a  = (const float*)d_in[20];
    const float* bhh_a  = (const float*)d_in[21];
    const float* Wm     = (const float*)d_in[22];
    const float* asrc_m = (const float*)d_in[23];
    const float* adst_m = (const float*)d_in[24];
    const float* bm     = (const float*)d_in[25];
    const float* Wih_m  = (const float*)d_in[26];
    const float* Whh_m  = (const float*)d_in[27];
    const float* bih_m  = (const float*)d_in[28];
    const float* bhh_m  = (const float*)d_in[29];
    const float* W2     = (const float*)d_in[30];
    const float* b2     = (const float*)d_in[31];
    float* out = (float*)d_out;

    const int N = in_sizes[0] / 64;
    const int E = in_sizes[1] / 2;
    const int G = out_size;
    const int* src = ei;
    const int* dst = ei + E;

    static int smem_set = 0;
    if (!smem_set) {
        cudaFuncSetAttribute(gemm_p, cudaFuncAttributeMaxDynamicSharedMemorySize, GEMM_SMEM);
        smem_set = 1;
    }

    float *X, *Z, *H, *GI, *GH, *al, *ar, *sum, *cE, *Wg1p;
    float *OUT, *OT, *H2, *GI2, *GH2, *ad;
    SYM(X, g_X); SYM(Z, g_Z); SYM(H, g_H); SYM(GI, g_GI); SYM(GH, g_GH);
    SYM(al, g_al); SYM(ar, g_ar); SYM(sum, g_sum);
    SYM(cE, g_cE); SYM(Wg1p, g_Wg1p);
    SYM(OUT, g_OUT); SYM(OT, g_OT); SYM(H2, g_H2);
    SYM(GI2, g_GI2); SYM(GH2, g_GH2); SYM(ad, g_ad);

    uint32_t *xih, *xil, *XAh, *XAl, *HAh, *HAl, *OAh, *OAl, *H2Ah, *H2Al;
    SYM(xih, g_xih); SYM(xil, g_xil);
    SYM(XAh, g_XAh); SYM(XAl, g_XAl); SYM(HAh, g_HAh); SYM(HAl, g_HAl);
    SYM(OAh, g_OAh); SYM(OAl, g_OAl); SYM(H2Ah, g_H2Ah); SYM(H2Al, g_H2Al);

    uint32_t *wW1h,*wW1l,*wWg1h,*wWg1l,*wWg2h,*wWg2l,*wWih0h,*wWih0l,*wWhh0h,*wWhh0l;
    uint32_t *wWah,*wWal,*wWihah,*wWihal,*wWhhah,*wWhhal,*wWmh,*wWml,*wWihmh,*wWihml,*wWhhmh,*wWhhml;
    SYM(wW1h, g_wW1h); SYM(wW1l, g_wW1l);
    SYM(wWg1h, g_wWg1h); SYM(wWg1l, g_wWg1l);
    SYM(wWg2h, g_wWg2h); SYM(wWg2l, g_wWg2l);
    SYM(wWih0h, g_wWih0h); SYM(wWih0l, g_wWih0l);
    SYM(wWhh0h, g_wWhh0h); SYM(wWhh0l, g_wWhh0l);
    SYM(wWah, g_wWah); SYM(wWal, g_wWal);
    SYM(wWihah, g_wWihah); SYM(wWihal, g_wWihal);
    SYM(wWhhah, g_wWhhah); SYM(wWhhal, g_wWhhal);
    SYM(wWmh, g_wWmh); SYM(wWml, g_wWml);
    SYM(wWihmh, g_wWihmh); SYM(wWihml, g_wWihml);
    SYM(wWhhmh, g_wWhhmh); SYM(wWhhml, g_wWhhml);

    auto split = [&](const float* A, uint32_t* hi, uint32_t* lo, int pairs) {
        split_mat<<<cdiv(pairs, 256), 256>>>(A, hi, lo, pairs);
    };
    auto gemm = [&](const uint32_t* Ah, const uint32_t* Al,
                    const uint32_t* Wh, const uint32_t* Wl,
                    const float* bias, float* C, uint32_t* Chi, uint32_t* Clo,
                    int n, int mm, int k, int act) {
        dim3 grid(mm / 128, cdiv(n, 64));
        gemm_p<<<grid, 256, GEMM_SMEM>>>(Ah, Al, Wh, Wl, bias, C, Chi, Clo, n, mm, k, act);
    };

    const int T256_NC  = cdiv(N * HIDC, 256);
    const int T256_NP  = cdiv(N * 64, 256);
    const int WARP_E   = cdiv(E * 32, 256);
    const int WARP_N   = cdiv(N * 32, 256);

    auto message_pass = [&](const float* bias_vec) {
        fill_sum_H   <<<T256_NC, 256>>>(sum, H, N);
        edge_scatter_f<<<WARP_E, 256>>>(src, dst, E, al, ar, sum, Z, H);
        bias_elu_split<<<T256_NP, 256>>>(H, sum, bias_vec, HAh, HAl, N);
    };

    // ---- weight prep ----
    comp_cedge<<<1, 128>>>(Wg1, cE);
    pack_wg1<<<64, 256>>>(Wg1, Wg1p);
    split(W1,   wW1h,   wW1l,   128 * 32);
    split(Wg1p, wWg1h,  wWg1l,  128 * 64);
    split(Wg2,  wWg2h,  wWg2l,  128 * 64);
    split(Wih0, wWih0h, wWih0l, 384 * 64);
    split(Whh0, wWhh0h, wWhh0l, 384 * 64);
    split(Wa,   wWah,   wWal,   2 * 128 * 64);
    split(Wih_a, wWihah, wWihal, 2 * 384 * 64);
    split(Whh_a, wWhhah, wWhhal, 2 * 384 * 64);
    split(Wm,   wWmh,   wWml,   128 * 64);
    split(Wih_m, wWihmh, wWihml, 384 * 64);
    split(Whh_m, wWhhmh, wWhhml, 384 * 64);

    // ---- Stage 0: X = leaky(x @ W1^T + b1), planes emitted ----
    split(x, xih, xil, N * 32);
    gemm(xih, xil, wW1h, wW1l, b1, X, XAh, XAl, N, 128, 64, 1);

    // ---- Stage 1: GATEConv + GRU ----
    gemm(XAh, XAl, wWg1h, wWg1l, cE, H, nullptr, nullptr, N, 128, 128, 1);
    rowdot_ab<<<WARP_N, 256>>>(H, att_l, X, att_r, al, ar, N);
    gemm(XAh, XAl, wWg2h, wWg2l, nullptr, Z, nullptr, nullptr, N, 128, 128, 0);
    message_pass(bg);
    gemm(HAh, HAl, wWih0h, wWih0l, bih0, GI, nullptr, nullptr, N, 384, 128, 0);
    gemm(XAh, XAl, wWhh0h, wWhh0l, bhh0, GH, nullptr, nullptr, N, 384, 128, 0);
    gru_gate_split<<<T256_NP, 256>>>(GI, GH, X, XAh, XAl, N);

    // ---- Stage 2: 2 x (GATConv + GRU) ----
    for (int l = 0; l < 2; l++) {
        gemm(XAh, XAl, wWah + (size_t)l * 128 * 64, wWal + (size_t)l * 128 * 64,
             nullptr, Z, nullptr, nullptr, N, 128, 128, 0);
        rowdot2<<<WARP_N, 256>>>(Z, asrc_a + l * HIDC, adst_a + l * HIDC, al, ar, N);
        message_pass(ba + l * HIDC);
        gemm(HAh, HAl, wWihah + (size_t)l * 384 * 64, wWihal + (size_t)l * 384 * 64,
             bih_a + l * H3C, GI, nullptr, nullptr, N, 384, 128, 0);
        gemm(XAh, XAl, wWhhah + (size_t)l * 384 * 64, wWhhal + (size_t)l * 384 * 64,
             bhh_a + l * H3C, GH, nullptr, nullptr, N, 384, 128, 0);
        gru_gate_split<<<T256_NP, 256>>>(GI, GH, X, XAh, XAl, N);
    }

    // ---- Stage 3: attentive readout ----
    const int T256_GC = cdiv(G * HIDC, 256);
    const int T256_GP = cdiv(G * 64, 256);
    const int WARP_G  = cdiv(G * 32, 256);

    fill_f32<<<T256_GC, 256>>>(OUT, 0.f, G * HIDC);
    node_scatter_sum<<<WARP_N, 256>>>(batch, X, OUT, N);
    relu_split<<<T256_GP, 256>>>(OUT, OAh, OAl, G);

    gemm(XAh, XAl, wWmh, wWml, nullptr, Z, nullptr, nullptr, N, 128, 128, 0);
    rowdot<<<WARP_N, 256>>>(Z, asrc_m, al, N);

    for (int t = 0; t < 3; t++) {
        gemm(OAh, OAl, wWmh, wWml, nullptr, OT, nullptr, nullptr, G, 128, 128, 0);
        rowdot<<<WARP_G, 256>>>(OT, adst_m, ad, G);
        fill_sum_H<<<T256_GC, 256>>>(sum, H2, G);
        node_scatter_f<<<WARP_N, 256>>>(batch, N, al, ad, sum, Z, H2);
        bias_elu_split<<<T256_GP, 256>>>(H2, sum, bm, H2Ah, H2Al, G);
        gemm(H2Ah, H2Al, wWihmh, wWihml, bih_m, GI2, nullptr, nullptr, G, 384, 128, 0);
        gemm(OAh, OAl, wWhhmh, wWhhml, bhh_m, GH2, nullptr, nullptr, G, 384, 128, 0);
        gru_gate_split<<<T256_GP, 256>>>(GI2, GH2, OUT, OAh, OAl, G);
    }

    final_out<<<WARP_G, 256>>>(OUT, W2, b2, out, G);
}

// round 15
// speedup vs baseline: 3.3648x; 1.2117x over previous
#include <cuda_runtime.h>
#include <cuda_bf16.h>
#include <math.h>
#include <stdint.h>

// ---------------------------------------------------------------------------
// Problem constants
// ---------------------------------------------------------------------------
#define NMAX   50000
#define EMAX   800000
#define GMAX   1024
#define HIDC   128
#define H3C    384
#define NEGS   0.01f

// ---------------------------------------------------------------------------
// Scratch (device globals; no allocation allowed)
// ---------------------------------------------------------------------------
__device__ float g_X  [(size_t)NMAX * HIDC];
__device__ float g_Z  [(size_t)NMAX * HIDC];
__device__ float g_H  [(size_t)NMAX * HIDC];
__device__ float g_GI [(size_t)NMAX * H3C];
__device__ float g_GH [(size_t)NMAX * H3C];
__device__ float g_al [NMAX];
__device__ float g_ar [NMAX];
__device__ float g_cE [HIDC];
__device__ float g_Wg1p[HIDC * HIDC];
__device__ float g_OUT [GMAX * HIDC];
__device__ float g_OT  [GMAX * HIDC];
__device__ float g_GI2 [GMAX * H3C];
__device__ float g_GH2 [GMAX * H3C];
__device__ float g_ad  [GMAX];

// CSR for edges grouped by dst + graph bounds for sorted batch
__device__ int g_deg   [NMAX];
__device__ int g_rowptr[NMAX + 1];
__device__ int g_cursor[NMAX];
__device__ int g_col   [EMAX];
__device__ int g_gptr  [GMAX + 1];

// bf16 hi/lo planes (packed pairs, u32 = 2 bf16)
__device__ uint32_t g_xih[(size_t)NMAX * 32], g_xil[(size_t)NMAX * 32];
__device__ uint32_t g_XAh[(size_t)NMAX * 64], g_XAl[(size_t)NMAX * 64];
__device__ uint32_t g_HAh[(size_t)NMAX * 64], g_HAl[(size_t)NMAX * 64];
__device__ uint32_t g_OAh[GMAX * 64],  g_OAl[GMAX * 64];
__device__ uint32_t g_H2Ah[GMAX * 64], g_H2Al[GMAX * 64];
// weight planes
__device__ uint32_t g_wW1h[128 * 32],  g_wW1l[128 * 32];
__device__ uint32_t g_wWg1h[128 * 64], g_wWg1l[128 * 64];
__device__ uint32_t g_wWg2h[128 * 64], g_wWg2l[128 * 64];
__device__ uint32_t g_wWih0h[384 * 64], g_wWih0l[384 * 64];
__device__ uint32_t g_wWhh0h[384 * 64], g_wWhh0l[384 * 64];
__device__ uint32_t g_wWah[2 * 128 * 64], g_wWal[2 * 128 * 64];
__device__ uint32_t g_wWihah[2 * 384 * 64], g_wWihal[2 * 384 * 64];
__device__ uint32_t g_wWhhah[2 * 384 * 64], g_wWhhal[2 * 384 * 64];
__device__ uint32_t g_wWmh[128 * 64],  g_wWml[128 * 64];
__device__ uint32_t g_wWihmh[384 * 64], g_wWihml[384 * 64];
__device__ uint32_t g_wWhhmh[384 * 64], g_wWhhml[384 * 64];

// ---------------------------------------------------------------------------
// Helpers
// ---------------------------------------------------------------------------
__device__ __forceinline__ float leaky_f(float v) { return v >= 0.f ? v : NEGS * v; }

__device__ __forceinline__ void split2(float a, float b, uint32_t& hi, uint32_t& lo) {
    __nv_bfloat16 ah = __float2bfloat16_rn(a);
    __nv_bfloat16 bh = __float2bfloat16_rn(b);
    __nv_bfloat162 h; h.x = ah; h.y = bh;
    hi = *reinterpret_cast<uint32_t*>(&h);
    __nv_bfloat162 l;
    l.x = __float2bfloat16_rn(a - __bfloat162float(ah));
    l.y = __float2bfloat16_rn(b - __bfloat162float(bh));
    lo = *reinterpret_cast<uint32_t*>(&l);
}

__device__ __forceinline__ void mma_bf16(float c[4], const uint32_t a[4], const uint32_t b[2]) {
    asm volatile("mma.sync.aligned.m16n8k16.row.col.f32.bf16.bf16.f32 "
        "{%0,%1,%2,%3}, {%4,%5,%6,%7}, {%8,%9}, {%0,%1,%2,%3};"
        : "+f"(c[0]), "+f"(c[1]), "+f"(c[2]), "+f"(c[3])
        : "r"(a[0]), "r"(a[1]), "r"(a[2]), "r"(a[3]), "r"(b[0]), "r"(b[1]));
}

__device__ __forceinline__ void cp16(uint32_t* s, const uint32_t* g) {
    uint32_t sa = (uint32_t)__cvta_generic_to_shared(s);
    asm volatile("cp.async.cg.shared.global [%0], [%1], 16;" :: "r"(sa), "l"(g));
}

// ---------------------------------------------------------------------------
// Split matrix into bf16 hi/lo packed planes (weights + input x only)
// ---------------------------------------------------------------------------
__global__ void split_mat(const float* __restrict__ A, uint32_t* __restrict__ hi,
                          uint32_t* __restrict__ lo, int pairs)
{
    int i = blockIdx.x * blockDim.x + threadIdx.x;
    if (i >= pairs) return;
    float2 v = reinterpret_cast<const float2*>(A)[i];
    uint32_t h, l;
    split2(v.x, v.y, h, l);
    hi[i] = h; lo[i] = l;
}

// ---------------------------------------------------------------------------
// Plane GEMM (unchanged from R11 passing kernel): BM=64, BN=128, K resident.
// ---------------------------------------------------------------------------
#define SP 68
#define GEMM_SMEM ((2 * 64 + 2 * 128) * SP * 4)

__global__ __launch_bounds__(256)
void gemm_p(const uint32_t* __restrict__ Ah, const uint32_t* __restrict__ Al,
            const uint32_t* __restrict__ Wh, const uint32_t* __restrict__ Wl,
            const float* __restrict__ bias, float* __restrict__ C,
            uint32_t* __restrict__ Chi, uint32_t* __restrict__ Clo,
            int N, int M, int K, int act)
{
    extern __shared__ uint32_t smem[];
    uint32_t* sAh = smem;
    uint32_t* sAl = smem + 64 * SP;
    uint32_t* sWh = smem + 2 * 64 * SP;
    uint32_t* sWl = smem + 2 * 64 * SP + 128 * SP;

    const int tid  = threadIdx.x;
    const int lane = tid & 31;
    const int warp = tid >> 5;
    const int gID  = lane >> 2;
    const int tig  = lane & 3;
    const int row0 = blockIdx.y * 64;
    const int col0 = blockIdx.x * 128;
    const int warpM = (warp >> 2) * 32;
    const int warpN = (warp & 3) * 32;

    const int kp  = K >> 1;
    const int kp4 = kp >> 2;
    const int sh  = (kp4 == 16) ? 4 : 3;
    const int msk = kp4 - 1;

    for (int s = tid; s < 64 * kp4; s += 256) {
        int r = s >> sh, c = (s & msk) << 2;
        int gr = row0 + r;
        if (gr < N) {
            cp16(&sAh[r * SP + c], Ah + (size_t)gr * kp + c);
            cp16(&sAl[r * SP + c], Al + (size_t)gr * kp + c);
        }
    }
    for (int s = tid; s < 128 * kp4; s += 256) {
        int r = s >> sh, c = (s & msk) << 2;
        int gw = col0 + r;
        cp16(&sWh[r * SP + c], Wh + (size_t)gw * kp + c);
        cp16(&sWl[r * SP + c], Wl + (size_t)gw * kp + c);
    }
    asm volatile("cp.async.commit_group;");
    asm volatile("cp.async.wait_group 0;");
    __syncthreads();

    float c[2][4][4];
    #pragma unroll
    for (int i = 0; i < 2; i++)
        #pragma unroll
        for (int j = 0; j < 4; j++)
            #pragma unroll
            for (int q = 0; q < 4; q++) c[i][j][q] = 0.f;

    const int nks = K >> 4;
    for (int ks = 0; ks < nks; ks++) {
        const int pb = ks * 8;
        uint32_t ah[2][4], alr[2][4], bh[4][2], blr[4][2];
        #pragma unroll
        for (int i = 0; i < 2; i++) {
            int b0 = (warpM + i * 16 + gID) * SP + pb + tig;
            int b8 = b0 + 8 * SP;
            ah[i][0] = sAh[b0];     ah[i][1] = sAh[b8];
            ah[i][2] = sAh[b0 + 4]; ah[i][3] = sAh[b8 + 4];
            alr[i][0] = sAl[b0];     alr[i][1] = sAl[b8];
            alr[i][2] = sAl[b0 + 4]; alr[i][3] = sAl[b8 + 4];
        }
        #pragma unroll
        for (int j = 0; j < 4; j++) {
            int wb = (warpN + j * 8 + gID) * SP + pb + tig;
            bh[j][0] = sWh[wb]; bh[j][1] = sWh[wb + 4];
            blr[j][0] = sWl[wb]; blr[j][1] = sWl[wb + 4];
        }
        #pragma unroll
        for (int i = 0; i < 2; i++)
            #pragma unroll
            for (int j = 0; j < 4; j++) mma_bf16(c[i][j], ah[i], bh[j]);
        #pragma unroll
        for (int i = 0; i < 2; i++)
            #pragma unroll
            for (int j = 0; j < 4; j++) mma_bf16(c[i][j], alr[i], bh[j]);
        #pragma unroll
        for (int i = 0; i < 2; i++)
            #pragma unroll
            for (int j = 0; j < 4; j++) mma_bf16(c[i][j], ah[i], blr[j]);
    }

    const int mp = M >> 1;
    #pragma unroll
    for (int i = 0; i < 2; i++) {
        int r_lo = row0 + warpM + i * 16 + gID;
        int r_hi = r_lo + 8;
        #pragma unroll
        for (int j = 0; j < 4; j++) {
            int cc = col0 + warpN + j * 8 + tig * 2;
            float b0 = bias ? bias[cc] : 0.f;
            float b1 = bias ? bias[cc + 1] : 0.f;
            float v0 = c[i][j][0] + b0, v1 = c[i][j][1] + b1;
            float v2 = c[i][j][2] + b0, v3 = c[i][j][3] + b1;
            if (act == 1) { v0 = leaky_f(v0); v1 = leaky_f(v1); v2 = leaky_f(v2); v3 = leaky_f(v3); }
            if (r_lo < N) {
                C[(size_t)r_lo * M + cc]     = v0;
                C[(size_t)r_lo * M + cc + 1] = v1;
                if (Chi) {
                    uint32_t h, l; split2(v0, v1, h, l);
                    Chi[(size_t)r_lo * mp + (cc >> 1)] = h;
                    Clo[(size_t)r_lo * mp + (cc >> 1)] = l;
                }
            }
            if (r_hi < N) {
                C[(size_t)r_hi * M + cc]     = v2;
                C[(size_t)r_hi * M + cc + 1] = v3;
                if (Chi) {
                    uint32_t h, l; split2(v2, v3, h, l);
                    Chi[(size_t)r_hi * mp + (cc >> 1)] = h;
                    Clo[(size_t)r_hi * mp + (cc >> 1)] = l;
                }
            }
        }
    }
}

// ---------------------------------------------------------------------------
// CSR build (once per launch)
// ---------------------------------------------------------------------------
__global__ void zero_i32(int* p, int n) {
    int i = blockIdx.x * blockDim.x + threadIdx.x;
    if (i < n) p[i] = 0;
}

__global__ void deg_count(const int* __restrict__ dst, int E, int* __restrict__ deg) {
    int e = blockIdx.x * blockDim.x + threadIdx.x;
    if (e < E) atomicAdd(&deg[dst[e]], 1);
}

// single-block exclusive scan (warp-shfl based), writes rowptr + cursor
__global__ void scan_deg(const int* __restrict__ deg, int* __restrict__ rowptr,
                         int* __restrict__ cursor, int N)
{
    __shared__ int wsum_s[32];
    __shared__ int carry_s;
    int tid = threadIdx.x, lane = tid & 31, wid = tid >> 5;
    if (tid == 0) carry_s = 0;
    __syncthreads();
    for (int base = 0; base < N; base += 1024) {
        int i = base + tid;
        int v = (i < N) ? deg[i] : 0;
        int x = v;
        #pragma unroll
        for (int off = 1; off < 32; off <<= 1) {
            int t = __shfl_up_sync(0xFFFFFFFFu, x, off);
            if (lane >= off) x += t;
        }
        if (lane == 31) wsum_s[wid] = x;
        __syncthreads();
        if (wid == 0) {
            int y = wsum_s[lane];
            #pragma unroll
            for (int off = 1; off < 32; off <<= 1) {
                int t = __shfl_up_sync(0xFFFFFFFFu, y, off);
                if (lane >= off) y += t;
            }
            wsum_s[lane] = y;
        }
        __syncthreads();
        int warpoff = (wid > 0) ? wsum_s[wid - 1] : 0;
        int excl = carry_s + warpoff + x - v;
        if (i < N) { rowptr[i] = excl; cursor[i] = excl; }
        __syncthreads();
        if (tid == 1023) carry_s += wsum_s[31];
        __syncthreads();
    }
    if (threadIdx.x == 0) rowptr[N] = carry_s;
}

__global__ void csr_fill(const int* __restrict__ src, const int* __restrict__ dst, int E,
                         int* __restrict__ cursor, int* __restrict__ col)
{
    int e = blockIdx.x * blockDim.x + threadIdx.x;
    if (e >= E) return;
    int p = atomicAdd(&cursor[dst[e]], 1);
    col[p] = src[e];
}

// gptr[g] = first node index with batch >= g (batch sorted); g in [0, G]
__global__ void graph_bounds(const int* __restrict__ batch, int N, int G,
                             int* __restrict__ gptr)
{
    int g = blockIdx.x * blockDim.x + threadIdx.x;
    if (g > G) return;
    int lo = 0, hi = N;
    while (lo < hi) {
        int mid = (lo + hi) >> 1;
        if (batch[mid] < g) lo = mid + 1; else hi = mid;
    }
    gptr[g] = lo;
}

// ---------------------------------------------------------------------------
// Fused message pass: per-dst gather + softmax-normalize + bias + ELU + split
// One warp per node. Edge weights computed once per edge, shfl-broadcast.
// ---------------------------------------------------------------------------
__global__ void gather_msg(const int* __restrict__ rowptr, const int* __restrict__ col,
                           const float* __restrict__ al, const float* __restrict__ ar,
                           const float* __restrict__ Z, const float* __restrict__ bias,
                           uint32_t* __restrict__ Hh, uint32_t* __restrict__ Hl, int N)
{
    int gt = blockIdx.x * blockDim.x + threadIdx.x;
    int d = gt >> 5, lane = gt & 31;
    if (d >= N) return;
    int e0 = rowptr[d], e1 = rowptr[d + 1];
    float arD = ar[d];
    float4 acc = make_float4(0.f, 0.f, 0.f, 0.f);
    float wsum = 0.f;
    for (int eb = e0; eb < e1; eb += 32) {
        int ee = eb + lane;
        float wl = 0.f; int sl = 0;
        if (ee < e1) {
            sl = col[ee];
            wl = expf(leaky_f(al[sl] + arD));
        }
        int cnt = min(32, e1 - eb);
        for (int q = 0; q < cnt; q++) {
            float w = __shfl_sync(0xFFFFFFFFu, wl, q);
            int s   = __shfl_sync(0xFFFFFFFFu, sl, q);
            wsum += w;
            float4 z = reinterpret_cast<const float4*>(Z + (size_t)s * HIDC)[lane];
            acc.x += z.x * w; acc.y += z.y * w; acc.z += z.z * w; acc.w += z.w * w;
        }
    }
    float inv = 1.f / (wsum + 1e-16f);
    int c0 = lane * 4;
    float v0 = acc.x * inv + bias[c0];
    float v1 = acc.y * inv + bias[c0 + 1];
    float v2 = acc.z * inv + bias[c0 + 2];
    float v3 = acc.w * inv + bias[c0 + 3];
    v0 = v0 > 0.f ? v0 : expm1f(v0);
    v1 = v1 > 0.f ? v1 : expm1f(v1);
    v2 = v2 > 0.f ? v2 : expm1f(v2);
    v3 = v3 > 0.f ? v3 : expm1f(v3);
    uint32_t h, l;
    split2(v0, v1, h, l);
    Hh[(size_t)d * 64 + 2 * lane]     = h;
    Hl[(size_t)d * 64 + 2 * lane]     = l;
    split2(v2, v3, h, l);
    Hh[(size_t)d * 64 + 2 * lane + 1] = h;
    Hl[(size_t)d * 64 + 2 * lane + 1] = l;
}

// Readout: per-graph sum of X rows + relu, writes OUT f32 + planes
__global__ void gather_sum_relu(const int* __restrict__ gptr, const float* __restrict__ X,
                                float* __restrict__ OUT,
                                uint32_t* __restrict__ Oh, uint32_t* __restrict__ Ol, int G)
{
    int gt = blockIdx.x * blockDim.x + threadIdx.x;
    int g = gt >> 5, lane = gt & 31;
    if (g >= G) return;
    int n0 = gptr[g], n1 = gptr[g + 1];
    float4 acc = make_float4(0.f, 0.f, 0.f, 0.f);
    for (int n = n0; n < n1; n++) {
        float4 v = reinterpret_cast<const float4*>(X + (size_t)n * HIDC)[lane];
        acc.x += v.x; acc.y += v.y; acc.z += v.z; acc.w += v.w;
    }
    acc.x = fmaxf(acc.x, 0.f); acc.y = fmaxf(acc.y, 0.f);
    acc.z = fmaxf(acc.z, 0.f); acc.w = fmaxf(acc.w, 0.f);
    reinterpret_cast<float4*>(OUT + (size_t)g * HIDC)[lane] = acc;
    uint32_t h, l;
    split2(acc.x, acc.y, h, l);
    Oh[(size_t)g * 64 + 2 * lane]     = h;
    Ol[(size_t)g * 64 + 2 * lane]     = l;
    split2(acc.z, acc.w, h, l);
    Oh[(size_t)g * 64 + 2 * lane + 1] = h;
    Ol[(size_t)g * 64 + 2 * lane + 1] = l;
}

// Readout attention gather: per-graph weighted sum + normalize + bias + ELU + split
__global__ void gather_att(const int* __restrict__ gptr, const float* __restrict__ al,
                           const float* __restrict__ ad, const float* __restrict__ Z,
                           const float* __restrict__ bm,
                           uint32_t* __restrict__ Hh, uint32_t* __restrict__ Hl, int G)
{
    int gt = blockIdx.x * blockDim.x + threadIdx.x;
    int g = gt >> 5, lane = gt & 31;
    if (g >= G) return;
    int n0 = gptr[g], n1 = gptr[g + 1];
    float adg = ad[g];
    float4 acc = make_float4(0.f, 0.f, 0.f, 0.f);
    float wsum = 0.f;
    for (int nb = n0; nb < n1; nb += 32) {
        int nn = nb + lane;
        float wl = 0.f;
        if (nn < n1) wl = expf(leaky_f(al[nn] + adg));
        int cnt = min(32, n1 - nb);
        for (int q = 0; q < cnt; q++) {
            float w = __shfl_sync(0xFFFFFFFFu, wl, q);
            wsum += w;
            float4 z = reinterpret_cast<const float4*>(Z + (size_t)(nb + q) * HIDC)[lane];
            acc.x += z.x * w; acc.y += z.y * w; acc.z += z.z * w; acc.w += z.w * w;
        }
    }
    float inv = 1.f / (wsum + 1e-16f);
    int c0 = lane * 4;
    float v0 = acc.x * inv + bm[c0];
    float v1 = acc.y * inv + bm[c0 + 1];
    float v2 = acc.z * inv + bm[c0 + 2];
    float v3 = acc.w * inv + bm[c0 + 3];
    v0 = v0 > 0.f ? v0 : expm1f(v0);
    v1 = v1 > 0.f ? v1 : expm1f(v1);
    v2 = v2 > 0.f ? v2 : expm1f(v2);
    v3 = v3 > 0.f ? v3 : expm1f(v3);
    uint32_t h, l;
    split2(v0, v1, h, l);
    Hh[(size_t)g * 64 + 2 * lane]     = h;
    Hl[(size_t)g * 64 + 2 * lane]     = l;
    split2(v2, v3, h, l);
    Hh[(size_t)g * 64 + 2 * lane + 1] = h;
    Hl[(size_t)g * 64 + 2 * lane + 1] = l;
}

// ---------------------------------------------------------------------------
// Small elementwise / utility kernels
// ---------------------------------------------------------------------------
__global__ void comp_cedge(const float* __restrict__ Wg1, float* __restrict__ cE) {
    int m = threadIdx.x;
    if (m < HIDC) {
        float s = 0.f;
        #pragma unroll
        for (int j = 0; j < 25; j++) s += Wg1[(size_t)m * 153 + 128 + j];
        cE[m] = s;
    }
}

__global__ void pack_wg1(const float* __restrict__ Wg1, float* __restrict__ out) {
    int i = blockIdx.x * blockDim.x + threadIdx.x;
    if (i < HIDC * HIDC) {
        int r = i >> 7, c = i & 127;
        out[i] = Wg1[(size_t)r * 153 + c];
    }
}

__global__ void rowdot(const float* __restrict__ A, const float* __restrict__ v,
                       float* __restrict__ out, int N)
{
    int gt = blockIdx.x * blockDim.x + threadIdx.x;
    int row = gt >> 5, lane = gt & 31;
    if (row >= N) return;
    const float* a = A + (size_t)row * HIDC;
    float s = 0.f;
    #pragma unroll
    for (int i = 0; i < 4; i++) s += a[lane + i * 32] * v[lane + i * 32];
    #pragma unroll
    for (int off = 16; off; off >>= 1) s += __shfl_xor_sync(0xFFFFFFFFu, s, off);
    if (lane == 0) out[row] = s;
}

__global__ void rowdot2(const float* __restrict__ Z, const float* __restrict__ va,
                        const float* __restrict__ vb, float* __restrict__ al,
                        float* __restrict__ ar, int N)
{
    int gt = blockIdx.x * blockDim.x + threadIdx.x;
    int row = gt >> 5, lane = gt & 31;
    if (row >= N) return;
    const float* a = Z + (size_t)row * HIDC;
    float s = 0.f, t = 0.f;
    #pragma unroll
    for (int i = 0; i < 4; i++) {
        float z = a[lane + i * 32];
        s += z * va[lane + i * 32];
        t += z * vb[lane + i * 32];
    }
    #pragma unroll
    for (int off = 16; off; off >>= 1) {
        s += __shfl_xor_sync(0xFFFFFFFFu, s, off);
        t += __shfl_xor_sync(0xFFFFFFFFu, t, off);
    }
    if (lane == 0) { al[row] = s; ar[row] = t; }
}

__global__ void rowdot_ab(const float* __restrict__ A, const float* __restrict__ va,
                          const float* __restrict__ B, const float* __restrict__ vb,
                          float* __restrict__ al, float* __restrict__ ar, int N)
{
    int gt = blockIdx.x * blockDim.x + threadIdx.x;
    int row = gt >> 5, lane = gt & 31;
    if (row >= N) return;
    const float* a = A + (size_t)row * HIDC;
    const float* b = B + (size_t)row * HIDC;
    float s = 0.f, t = 0.f;
    #pragma unroll
    for (int i = 0; i < 4; i++) {
        s += a[lane + i * 32] * va[lane + i * 32];
        t += b[lane + i * 32] * vb[lane + i * 32];
    }
    #pragma unroll
    for (int off = 16; off; off >>= 1) {
        s += __shfl_xor_sync(0xFFFFFFFFu, s, off);
        t += __shfl_xor_sync(0xFFFFFFFFu, t, off);
    }
    if (lane == 0) { al[row] = s; ar[row] = t; }
}

__global__ void gru_gate_split(const float* __restrict__ GI, const float* __restrict__ GH,
                               float* __restrict__ X,
                               uint32_t* __restrict__ Xh, uint32_t* __restrict__ Xl, int N)
{
    int i = blockIdx.x * blockDim.x + threadIdx.x;
    if (i >= N * 64) return;
    int n = i >> 6, p = i & 63;
    const float* gi = GI + (size_t)n * H3C;
    const float* gh = GH + (size_t)n * H3C;
    float o01[2];
    #pragma unroll
    for (int q = 0; q < 2; q++) {
        int c = 2 * p + q;
        float r  = 1.f / (1.f + expf(-(gi[c]       + gh[c])));
        float z  = 1.f / (1.f + expf(-(gi[c + 128] + gh[c + 128])));
        float nn = tanhf(gi[c + 256] + r * gh[c + 256]);
        float o  = (1.f - z) * nn + z * X[(size_t)n * HIDC + c];
        o01[q] = fmaxf(o, 0.f);
        X[(size_t)n * HIDC + c] = o01[q];
    }
    uint32_t h, l; split2(o01[0], o01[1], h, l);
    Xh[i] = h; Xl[i] = l;
}

__global__ void final_out(const float* __restrict__ OUT, const float* __restrict__ W2,
                          const float* __restrict__ b2, float* __restrict__ out, int G)
{
    int gt = blockIdx.x * blockDim.x + threadIdx.x;
    int g = gt >> 5, lane = gt & 31;
    if (g >= G) return;
    const float* a = OUT + (size_t)g * HIDC;
    float s = 0.f;
    #pragma unroll
    for (int i = 0; i < 4; i++) s += a[lane + i * 32] * W2[lane + i * 32];
    #pragma unroll
    for (int off = 16; off; off >>= 1) s += __shfl_xor_sync(0xFFFFFFFFu, s, off);
    if (lane == 0) out[g] = s + b2[0];
}

// ---------------------------------------------------------------------------
// Host
// ---------------------------------------------------------------------------
static inline int cdiv(int a, int b) { return (a + b - 1) / b; }

#define SYM(var, sym) cudaGetSymbolAddress((void**)&var, sym)

extern "C" void kernel_launch(void* const* d_in, const int* in_sizes, int n_in,
                              void* d_out, int out_size)
{
    const float* x      = (const float*)d_in[0];
    const int*   ei     = (const int*)  d_in[1];
    const int*   batch  = (const int*)  d_in[2];
    const float* W1     = (const float*)d_in[3];
    const float* b1     = (const float*)d_in[4];
    const float* Wg1    = (const float*)d_in[5];
    const float* att_l  = (const float*)d_in[6];
    const float* att_r  = (const float*)d_in[7];
    const float* Wg2    = (const float*)d_in[8];
    const float* bg     = (const float*)d_in[9];
    const float* Wih0   = (const float*)d_in[10];
    const float* Whh0   = (const float*)d_in[11];
    const float* bih0   = (const float*)d_in[12];
    const float* bhh0   = (const float*)d_in[13];
    const float* Wa     = (const float*)d_in[14];
    const float* asrc_a = (const float*)d_in[15];
    const float* adst_a = (const float*)d_in[16];
    const float* ba     = (const float*)d_in[17];
    const float* Wih_a  = (const float*)d_in[18];
    const float* Whh_a  = (const float*)d_in[19];
    const float* bih_a  = (const float*)d_in[20];
    const float* bhh_a  = (const float*)d_in[21];
    const float* Wm     = (const float*)d_in[22];
    const float* asrc_m = (const float*)d_in[23];
    const float* adst_m = (const float*)d_in[24];
    const float* bm     = (const float*)d_in[25];
    const float* Wih_m  = (const float*)d_in[26];
    const float* Whh_m  = (const float*)d_in[27];
    const float* bih_m  = (const float*)d_in[28];
    const float* bhh_m  = (const float*)d_in[29];
    const float* W2     = (const float*)d_in[30];
    const float* b2     = (const float*)d_in[31];
    float* out = (float*)d_out;

    const int N = in_sizes[0] / 64;
    const int E = in_sizes[1] / 2;
    const int G = out_size;
    const int* src = ei;
    const int* dst = ei + E;

    static int smem_set = 0;
    if (!smem_set) {
        cudaFuncSetAttribute(gemm_p, cudaFuncAttributeMaxDynamicSharedMemorySize, GEMM_SMEM);
        smem_set = 1;
    }

    float *X, *Z, *H, *GI, *GH, *al, *ar, *cE, *Wg1p;
    float *OUT, *OT, *GI2, *GH2, *ad;
    SYM(X, g_X); SYM(Z, g_Z); SYM(H, g_H); SYM(GI, g_GI); SYM(GH, g_GH);
    SYM(al, g_al); SYM(ar, g_ar);
    SYM(cE, g_cE); SYM(Wg1p, g_Wg1p);
    SYM(OUT, g_OUT); SYM(OT, g_OT);
    SYM(GI2, g_GI2); SYM(GH2, g_GH2); SYM(ad, g_ad);

    int *deg, *rowptr, *cursor, *colA, *gptr;
    SYM(deg, g_deg); SYM(rowptr, g_rowptr); SYM(cursor, g_cursor);
    SYM(colA, g_col); SYM(gptr, g_gptr);

    uint32_t *xih, *xil, *XAh, *XAl, *HAh, *HAl, *OAh, *OAl, *H2Ah, *H2Al;
    SYM(xih, g_xih); SYM(xil, g_xil);
    SYM(XAh, g_XAh); SYM(XAl, g_XAl); SYM(HAh, g_HAh); SYM(HAl, g_HAl);
    SYM(OAh, g_OAh); SYM(OAl, g_OAl); SYM(H2Ah, g_H2Ah); SYM(H2Al, g_H2Al);

    uint32_t *wW1h,*wW1l,*wWg1h,*wWg1l,*wWg2h,*wWg2l,*wWih0h,*wWih0l,*wWhh0h,*wWhh0l;
    uint32_t *wWah,*wWal,*wWihah,*wWihal,*wWhhah,*wWhhal,*wWmh,*wWml,*wWihmh,*wWihml,*wWhhmh,*wWhhml;
    SYM(wW1h, g_wW1h); SYM(wW1l, g_wW1l);
    SYM(wWg1h, g_wWg1h); SYM(wWg1l, g_wWg1l);
    SYM(wWg2h, g_wWg2h); SYM(wWg2l, g_wWg2l);
    SYM(wWih0h, g_wWih0h); SYM(wWih0l, g_wWih0l);
    SYM(wWhh0h, g_wWhh0h); SYM(wWhh0l, g_wWhh0l);
    SYM(wWah, g_wWah); SYM(wWal, g_wWal);
    SYM(wWihah, g_wWihah); SYM(wWihal, g_wWihal);
    SYM(wWhhah, g_wWhhah); SYM(wWhhal, g_wWhhal);
    SYM(wWmh, g_wWmh); SYM(wWml, g_wWml);
    SYM(wWihmh, g_wWihmh); SYM(wWihml, g_wWihml);
    SYM(wWhhmh, g_wWhhmh); SYM(wWhhml, g_wWhhml);

    auto split = [&](const float* A, uint32_t* hi, uint32_t* lo, int pairs) {
        split_mat<<<cdiv(pairs, 256), 256>>>(A, hi, lo, pairs);
    };
    auto gemm = [&](const uint32_t* Ah, const uint32_t* Al,
                    const uint32_t* Wh, const uint32_t* Wl,
                    const float* bias, float* C, uint32_t* Chi, uint32_t* Clo,
                    int n, int mm, int k, int act) {
        dim3 grid(mm / 128, cdiv(n, 64));
        gemm_p<<<grid, 256, GEMM_SMEM>>>(Ah, Al, Wh, Wl, bias, C, Chi, Clo, n, mm, k, act);
    };

    const int T256_NP  = cdiv(N * 64, 256);
    const int T256_E   = cdiv(E, 256);
    const int WARP_N   = cdiv(N * 32, 256);

    // ---- CSR + graph-bounds build (once) ----
    zero_i32<<<cdiv(N, 256), 256>>>(deg, N);
    deg_count<<<T256_E, 256>>>(dst, E, deg);
    scan_deg<<<1, 1024>>>(deg, rowptr, cursor, N);
    csr_fill<<<T256_E, 256>>>(src, dst, E, cursor, colA);
    graph_bounds<<<cdiv(G + 1, 256), 256>>>(batch, N, G, gptr);

    // ---- weight prep ----
    comp_cedge<<<1, 128>>>(Wg1, cE);
    pack_wg1<<<64, 256>>>(Wg1, Wg1p);
    split(W1,   wW1h,   wW1l,   128 * 32);
    split(Wg1p, wWg1h,  wWg1l,  128 * 64);
    split(Wg2,  wWg2h,  wWg2l,  128 * 64);
    split(Wih0, wWih0h, wWih0l, 384 * 64);
    split(Whh0, wWhh0h, wWhh0l, 384 * 64);
    split(Wa,   wWah,   wWal,   2 * 128 * 64);
    split(Wih_a, wWihah, wWihal, 2 * 384 * 64);
    split(Whh_a, wWhhah, wWhhal, 2 * 384 * 64);
    split(Wm,   wWmh,   wWml,   128 * 64);
    split(Wih_m, wWihmh, wWihml, 384 * 64);
    split(Whh_m, wWhhmh, wWhhml, 384 * 64);

    // ---- Stage 0: X = leaky(x @ W1^T + b1), planes emitted ----
    split(x, xih, xil, N * 32);
    gemm(xih, xil, wW1h, wW1l, b1, X, XAh, XAl, N, 128, 64, 1);

    // ---- Stage 1: GATEConv + GRU ----
    gemm(XAh, XAl, wWg1h, wWg1l, cE, H, nullptr, nullptr, N, 128, 128, 1);
    rowdot_ab<<<WARP_N, 256>>>(H, att_l, X, att_r, al, ar, N);
    gemm(XAh, XAl, wWg2h, wWg2l, nullptr, Z, nullptr, nullptr, N, 128, 128, 0);
    gather_msg<<<WARP_N, 256>>>(rowptr, colA, al, ar, Z, bg, HAh, HAl, N);
    gemm(HAh, HAl, wWih0h, wWih0l, bih0, GI, nullptr, nullptr, N, 384, 128, 0);
    gemm(XAh, XAl, wWhh0h, wWhh0l, bhh0, GH, nullptr, nullptr, N, 384, 128, 0);
    gru_gate_split<<<T256_NP, 256>>>(GI, GH, X, XAh, XAl, N);

    // ---- Stage 2: 2 x (GATConv + GRU) ----
    for (int l = 0; l < 2; l++) {
        gemm(XAh, XAl, wWah + (size_t)l * 128 * 64, wWal + (size_t)l * 128 * 64,
             nullptr, Z, nullptr, nullptr, N, 128, 128, 0);
        rowdot2<<<WARP_N, 256>>>(Z, asrc_a + l * HIDC, adst_a + l * HIDC, al, ar, N);
        gather_msg<<<WARP_N, 256>>>(rowptr, colA, al, ar, Z, ba + l * HIDC, HAh, HAl, N);
        gemm(HAh, HAl, wWihah + (size_t)l * 384 * 64, wWihal + (size_t)l * 384 * 64,
             bih_a + l * H3C, GI, nullptr, nullptr, N, 384, 128, 0);
        gemm(XAh, XAl, wWhhah + (size_t)l * 384 * 64, wWhhal + (size_t)l * 384 * 64,
             bhh_a + l * H3C, GH, nullptr, nullptr, N, 384, 128, 0);
        gru_gate_split<<<T256_NP, 256>>>(GI, GH, X, XAh, XAl, N);
    }

    // ---- Stage 3: attentive readout ----
    const int T256_GP = cdiv(G * 64, 256);
    const int WARP_G  = cdiv(G * 32, 256);

    gather_sum_relu<<<WARP_G, 256>>>(gptr, X, OUT, OAh, OAl, G);

    gemm(XAh, XAl, wWmh, wWml, nullptr, Z, nullptr, nullptr, N, 128, 128, 0);
    rowdot<<<WARP_N, 256>>>(Z, asrc_m, al, N);

    for (int t = 0; t < 3; t++) {
        gemm(OAh, OAl, wWmh, wWml, nullptr, OT, nullptr, nullptr, G, 128, 128, 0);
        rowdot<<<WARP_G, 256>>>(OT, adst_m, ad, G);
        gather_att<<<WARP_G, 256>>>(gptr, al, ad, Z, bm, H2Ah, H2Al, G);
        gemm(H2Ah, H2Al, wWihmh, wWihml, bih_m, GI2, nullptr, nullptr, G, 384, 128, 0);
        gemm(OAh, OAl, wWhhmh, wWhhml, bhh_m, GH2, nullptr, nullptr, G, 384, 128, 0);
        gru_gate_split<<<T256_GP, 256>>>(GI2, GH2, OUT, OAh, OAl, G);
    }

    final_out<<<WARP_G, 256>>>(OUT, W2, b2, out, G);
}